// round 11
// baseline (speedup 1.0000x reference)
#include <cuda_runtime.h>
#include <cuda_bf16.h>
#include <stdint.h>

// ===========================================================================
// CavAttention via mma.sync bf16 hi/lo split precision
// Round 10: 512 threads/CTA (16 warps, 32x32 warp tiles) for latency hiding
//   prep: wqkv/wout -> bf16 hi/lo global images (padded pitch 136)
//   K1:   qkv = xp @ wqkv                 (HMMA)  -> g_qkv
//   K2:   masked softmax + P@V            (SIMT)  -> g_att
//   K3:   out = att @ wout + bias         (HMMA, transposed store)
// ===========================================================================

#define HW_   8448
#define NROWS 84480
#define NT    512

__device__ __align__(16) float g_qkv[(size_t)NROWS * 768];
__device__ __align__(16) float g_att[(size_t)NROWS * 256];
__device__ __align__(16) __nv_bfloat16 g_w1h[6 * 4 * 64 * 136];
__device__ __align__(16) __nv_bfloat16 g_w1l[6 * 4 * 64 * 136];
__device__ __align__(16) __nv_bfloat16 g_w2h[2 * 4 * 64 * 136];
__device__ __align__(16) __nv_bfloat16 g_w2l[2 * 4 * 64 * 136];

#define AP 264            // A smem pitch (bf16 elems): 528B ≡ 4 banks mod 32
#define BP 136            // B smem pitch: 272B ≡ 4 banks mod 32

#define CHUNK_B  17408                    // one 64x136 bf16 image (bytes)
#define BUF_B    (2 * CHUNK_B)            // hi + lo per chunk

// ----------------------------- helpers ------------------------------------
__device__ __forceinline__ uint32_t smem_u32(const void* p) {
    uint32_t a;
    asm("{ .reg .u64 t; cvta.to.shared.u64 t, %1; cvt.u32.u64 %0, t; }" : "=r"(a) : "l"(p));
    return a;
}
__device__ __forceinline__ float bres(float f) {
    return f - __bfloat162float(__float2bfloat16(f));
}
__device__ __forceinline__ uint64_t pack4(float a0, float a1, float a2, float a3) {
    uint64_t r = (uint64_t)__bfloat16_as_ushort(__float2bfloat16(a0));
    r |= (uint64_t)__bfloat16_as_ushort(__float2bfloat16(a1)) << 16;
    r |= (uint64_t)__bfloat16_as_ushort(__float2bfloat16(a2)) << 32;
    r |= (uint64_t)__bfloat16_as_ushort(__float2bfloat16(a3)) << 48;
    return r;
}
__device__ __forceinline__ void cpa16(uint32_t dst, const void* src) {
    asm volatile("cp.async.cg.shared.global [%0], [%1], 16;" :: "r"(dst), "l"(src));
}
#define CP_COMMIT() asm volatile("cp.async.commit_group;" ::: "memory")
#define CP_WAIT(n)  asm volatile("cp.async.wait_group %0;" :: "n"(n) : "memory")

__device__ __forceinline__ void ldmA(uint32_t* r, uint32_t addr) {
    asm volatile("ldmatrix.sync.aligned.m8n8.x4.shared.b16 {%0,%1,%2,%3}, [%4];"
                 : "=r"(r[0]), "=r"(r[1]), "=r"(r[2]), "=r"(r[3]) : "r"(addr));
}
__device__ __forceinline__ void ldmB(uint32_t* r, uint32_t addr) {
    asm volatile("ldmatrix.sync.aligned.m8n8.x2.trans.shared.b16 {%0,%1}, [%2];"
                 : "=r"(r[0]), "=r"(r[1]) : "r"(addr));
}
__device__ __forceinline__ void mma16816(float* c, const uint32_t* a, const uint32_t* b) {
    asm volatile("mma.sync.aligned.m16n8k16.row.col.f32.bf16.bf16.f32 "
                 "{%0,%1,%2,%3}, {%4,%5,%6,%7}, {%8,%9}, {%0,%1,%2,%3};"
                 : "+f"(c[0]), "+f"(c[1]), "+f"(c[2]), "+f"(c[3])
                 : "r"(a[0]), "r"(a[1]), "r"(a[2]), "r"(a[3]), "r"(b[0]), "r"(b[1]));
}

// merged-pass 64-deep K chunk. acc = warp tile 32x32 (16 warps).
// Per k16-step: 12 ldmatrix feeding 24 MMAs.
__device__ __forceinline__ void mma_chunk(float acc[2][4][4],
                                          uint32_t aHi, uint32_t aLo,
                                          uint32_t bHi, uint32_t bLo) {
    #pragma unroll
    for (int ks = 0; ks < 4; ++ks) {
        uint32_t ah[2][4], al[2][4], bh[4][2], bl[4][2];
        #pragma unroll
        for (int i = 0; i < 2; ++i) {
            ldmA(ah[i], aHi + (uint32_t)((i * 16 * AP + ks * 16) * 2));
            ldmA(al[i], aLo + (uint32_t)((i * 16 * AP + ks * 16) * 2));
        }
        #pragma unroll
        for (int j = 0; j < 4; ++j) {
            ldmB(bh[j], bHi + (uint32_t)((ks * 16 * BP + j * 8) * 2));
            ldmB(bl[j], bLo + (uint32_t)((ks * 16 * BP + j * 8) * 2));
        }
        #pragma unroll
        for (int i = 0; i < 2; ++i)
            #pragma unroll
            for (int j = 0; j < 4; ++j)
                mma16816(acc[i][j], ah[i], bh[j]);
        #pragma unroll
        for (int i = 0; i < 2; ++i)
            #pragma unroll
            for (int j = 0; j < 4; ++j)
                mma16816(acc[i][j], ah[i], bl[j]);
        #pragma unroll
        for (int i = 0; i < 2; ++i)
            #pragma unroll
            for (int j = 0; j < 4; ++j)
                mma16816(acc[i][j], al[i], bh[j]);
    }
}

// issue one B chunk (hi+lo) via cp.async; 1088 uint4 per image
__device__ __forceinline__ void stage_B(uint32_t dst, const __nv_bfloat16* srcH,
                                        const __nv_bfloat16* srcL, int tid) {
    const char* sH = (const char*)srcH;
    const char* sL = (const char*)srcL;
    for (int e = tid; e < 1088; e += NT) {
        cpa16(dst + e * 16, sH + e * 16);
        cpa16(dst + CHUNK_B + e * 16, sL + e * 16);
    }
    CP_COMMIT();
}

// ======================= prep: weight conversion ===========================
__global__ __launch_bounds__(256) void prep_w(const float* __restrict__ wqkv,
                                              const float* __restrict__ wout) {
    int idx = blockIdx.x * 256 + threadIdx.x;
    if (idx < 196608) {
        int n = idx & 127, kr = (idx >> 7) & 63, kc = (idx >> 13) & 3, nt = idx >> 15;
        float f = wqkv[(kc * 64 + kr) * 768 + nt * 128 + n];
        int o = ((nt * 4 + kc) * 64 + kr) * 136 + n;
        g_w1h[o] = __float2bfloat16(f);
        g_w1l[o] = __float2bfloat16(bres(f));
    } else {
        int t = idx - 196608;
        int n = t & 127, kr = (t >> 7) & 63, kc = (t >> 13) & 3, nt = t >> 15;
        float f = wout[(kc * 64 + kr) * 256 + nt * 128 + n];
        int o = ((nt * 4 + kc) * 64 + kr) * 136 + n;
        g_w2h[o] = __float2bfloat16(f);
        g_w2l[o] = __float2bfloat16(bres(f));
    }
}

// ======================= K1: QKV GEMM ======================================
// smem: AHI 0 (67584B), ALO 67584, B ring 135168 (2 x 34816) -> 204800
#define K_ALO  67584
#define K_BB   135168
#define K1_SMEM 204800

__global__ __launch_bounds__(NT, 1) void k1_qkv(const float* __restrict__ x) {
    extern __shared__ __align__(16) char sm[];
    const uint32_t sb = smem_u32(sm);
    const int tid = threadIdx.x, lane = tid & 31, wid = tid >> 5;
    const int wm = (wid & 3) * 32, wn = (wid >> 2) * 32;
    const int m0 = blockIdx.x * 128;

    stage_B(sb + K_BB, g_w1h, g_w1l, tid);     // prefetch chunk 0

    // stage A slab (transposed gather from x), hi/lo bf16
    for (int e = tid; e < 128 * 64; e += NT) {
        int row = e >> 6, k4 = (e & 63) << 2;
        int r = m0 + row, g = r / 5, l = r - g * 5, b = g / HW_, hw = g - b * HW_;
        const float4 v = *(const float4*)(x + ((size_t)((b * 5 + l) * HW_ + hw)) * 256 + k4);
        uint32_t off = (uint32_t)(row * AP + k4) * 2;
        *(uint64_t*)(sm + off) = pack4(v.x, v.y, v.z, v.w);
        *(uint64_t*)(sm + K_ALO + off) = pack4(bres(v.x), bres(v.y), bres(v.z), bres(v.w));
    }

    const uint32_t aoff = (uint32_t)(((wm + (lane & 15)) * AP + ((lane >> 4) << 3)) * 2);
    const uint32_t boff = (uint32_t)(((lane & 15) * BP + wn) * 2);

    float acc[2][4][4];
    for (int c = 0; c < 24; ++c) {             // chunk c = (nt = c/4, kc = c%4)
        const int kc = c & 3;
        if (kc == 0) {
            #pragma unroll
            for (int i = 0; i < 2; ++i)
                #pragma unroll
                for (int j = 0; j < 4; ++j)
                    #pragma unroll
                    for (int q = 0; q < 4; ++q) acc[i][j][q] = 0.f;
        }
        if (c > 0) __syncthreads();            // mma(c-1) complete -> buf free
        if (c + 1 < 24)
            stage_B(sb + K_BB + ((c + 1) & 1) * BUF_B,
                    g_w1h + (c + 1) * 8704, g_w1l + (c + 1) * 8704, tid);
        if (c + 1 < 24) { CP_WAIT(1); } else { CP_WAIT(0); }
        __syncthreads();                       // chunk c visible

        uint32_t bb = sb + K_BB + (c & 1) * BUF_B;
        mma_chunk(acc,
                  sb + aoff + (uint32_t)(kc * 64 * 2),
                  sb + K_ALO + aoff + (uint32_t)(kc * 64 * 2),
                  bb + boff, bb + CHUNK_B + boff);

        if (kc == 3) {
            const int nt = c >> 2;
            #pragma unroll
            for (int i = 0; i < 2; ++i) {
                int row = m0 + wm + i * 16 + (lane >> 2);
                #pragma unroll
                for (int j = 0; j < 4; ++j) {
                    int col = nt * 128 + wn + j * 8 + (lane & 3) * 2;
                    float* p = g_qkv + (size_t)row * 768 + col;
                    *(float2*)p = make_float2(acc[i][j][0], acc[i][j][1]);
                    *(float2*)(p + 8 * 768) = make_float2(acc[i][j][2], acc[i][j][3]);
                }
            }
        }
    }
}

// ======================= K2: masked softmax attention (SIMT) ===============
#define K2_STR 769
#define K2_SMEM (20 * K2_STR * 4 + 100 * 4 + 20 * 4)

__global__ __launch_bounds__(128) void k2_attn(const int* __restrict__ mask) {
    extern __shared__ __align__(16) float sl[];           // [20][769]
    float* sc = sl + 20 * K2_STR;                         // [4][25]
    int*   ms = (int*)(sc + 100);                         // [20]
    const int tid = threadIdx.x;
    const int r0 = blockIdx.x * 20;
    const int g0 = blockIdx.x * 4;

    for (int e = tid; e < 20; e += 128) ms[e] = mask[g0 * 5 + e];
    for (int e = tid; e < 20 * 192; e += 128) {
        int row = e / 192, c4 = (e % 192) * 4;
        const float4 v = *(const float4*)(g_qkv + (size_t)(r0 + row) * 768 + c4);
        float* d = sl + row * K2_STR + c4;
        d[0] = v.x; d[1] = v.y; d[2] = v.z; d[3] = v.w;
    }
    __syncthreads();

    const float scale = 0.17677669529663687f;
    for (int h = 0; h < 8; ++h) {
        const int hc = h * 32;
        if (tid < 100) {
            int g = tid / 25, rr = tid % 25, i = rr / 5, j = rr % 5;
            float s;
            if (ms[g * 5 + j] == 0) s = -1e30f;
            else {
                const float* q = sl + (g * 5 + i) * K2_STR + hc;
                const float* k = sl + (g * 5 + j) * K2_STR + 256 + hc;
                s = 0.f;
                #pragma unroll
                for (int d = 0; d < 32; ++d) s = fmaf(q[d], k[d], s);
                s *= scale;
            }
            sc[tid] = s;
        }
        __syncthreads();
        if (tid < 20) {
            float* r = sc + (tid / 5) * 25 + (tid % 5) * 5;
            float mx = r[0];
            #pragma unroll
            for (int j = 1; j < 5; ++j) mx = fmaxf(mx, r[j]);
            float ev[5], s = 0.f;
            #pragma unroll
            for (int j = 0; j < 5; ++j) { ev[j] = __expf(r[j] - mx); s += ev[j]; }
            float inv = 1.f / s;
            #pragma unroll
            for (int j = 0; j < 5; ++j) r[j] = ev[j] * inv;
        }
        __syncthreads();
        for (int e = tid; e < 20 * 32; e += 128) {
            int row = e >> 5, d = e & 31;
            int g = row / 5, i = row - g * 5;
            const float* p = sc + g * 25 + i * 5;
            const float* v = sl + (g * 5) * K2_STR + 512 + hc + d;
            float o = 0.f;
            #pragma unroll
            for (int j = 0; j < 5; ++j) o = fmaf(p[j], v[j * K2_STR], o);
            g_att[(size_t)(r0 + row) * 256 + hc + d] = o;
        }
        __syncthreads();
    }
}

// ======================= K3: output GEMM + bias + transposed store =========
#define K3_BIAS 204800
#define K3_SMEM 205824

__global__ __launch_bounds__(NT, 1) void k3_out(const float* __restrict__ bout,
                                                float* __restrict__ out) {
    extern __shared__ __align__(16) char sm[];
    const uint32_t sb = smem_u32(sm);
    const int tid = threadIdx.x, lane = tid & 31, wid = tid >> 5;
    const int wm = (wid & 3) * 32, wn = (wid >> 2) * 32;
    const int m0 = blockIdx.x * 128;

    stage_B(sb + K_BB, g_w2h, g_w2l, tid);     // prefetch chunk 0

    if (tid < 256) ((float*)(sm + K3_BIAS))[tid] = bout[tid];

    for (int e = tid; e < 128 * 64; e += NT) {
        int row = e >> 6, k4 = (e & 63) << 2;
        const float4 v = *(const float4*)(g_att + (size_t)(m0 + row) * 256 + k4);
        uint32_t off = (uint32_t)(row * AP + k4) * 2;
        *(uint64_t*)(sm + off) = pack4(v.x, v.y, v.z, v.w);
        *(uint64_t*)(sm + K_ALO + off) = pack4(bres(v.x), bres(v.y), bres(v.z), bres(v.w));
    }

    const uint32_t aoff = (uint32_t)(((wm + (lane & 15)) * AP + ((lane >> 4) << 3)) * 2);
    const uint32_t boff = (uint32_t)(((lane & 15) * BP + wn) * 2);
    const float* bias = (const float*)(sm + K3_BIAS);

    float acc[2][4][4];
    for (int c = 0; c < 8; ++c) {
        const int kc = c & 3;
        if (kc == 0) {
            #pragma unroll
            for (int i = 0; i < 2; ++i)
                #pragma unroll
                for (int j = 0; j < 4; ++j)
                    #pragma unroll
                    for (int q = 0; q < 4; ++q) acc[i][j][q] = 0.f;
        }
        if (c > 0) __syncthreads();
        if (c + 1 < 8)
            stage_B(sb + K_BB + ((c + 1) & 1) * BUF_B,
                    g_w2h + (c + 1) * 8704, g_w2l + (c + 1) * 8704, tid);
        if (c + 1 < 8) { CP_WAIT(1); } else { CP_WAIT(0); }
        __syncthreads();

        uint32_t bb = sb + K_BB + (c & 1) * BUF_B;
        mma_chunk(acc,
                  sb + aoff + (uint32_t)(kc * 64 * 2),
                  sb + K_ALO + aoff + (uint32_t)(kc * 64 * 2),
                  bb + boff, bb + CHUNK_B + boff);

        if (kc == 3) {
            const int nt = c >> 2;
            #pragma unroll
            for (int i = 0; i < 2; ++i) {
                int r1 = m0 + wm + i * 16 + (lane >> 2);
                #pragma unroll
                for (int rr = 0; rr < 2; ++rr) {
                    int r = r1 + rr * 8;
                    int g = r / 5, l = r - g * 5, b = g / HW_, hw = g - b * HW_;
                    float* dst = out + ((size_t)((b * 5 + l) * HW_ + hw)) * 256;
                    #pragma unroll
                    for (int j = 0; j < 4; ++j) {
                        int col = nt * 128 + wn + j * 8 + (lane & 3) * 2;
                        float2 o = make_float2(acc[i][j][2 * rr] + bias[col],
                                               acc[i][j][2 * rr + 1] + bias[col + 1]);
                        *(float2*)(dst + col) = o;
                    }
                }
            }
        }
    }
}

// ===========================================================================
extern "C" void kernel_launch(void* const* d_in, const int* in_sizes, int n_in,
                              void* d_out, int out_size) {
    const float* x    = (const float*)d_in[0];
    const int*   mask = (const int*)d_in[1];
    const float* wqkv = (const float*)d_in[2];
    const float* wout = (const float*)d_in[3];
    const float* bout = (const float*)d_in[4];
    float*       out  = (float*)d_out;

    cudaFuncSetAttribute(k1_qkv, cudaFuncAttributeMaxDynamicSharedMemorySize, K1_SMEM);
    cudaFuncSetAttribute(k2_attn, cudaFuncAttributeMaxDynamicSharedMemorySize, K2_SMEM);
    cudaFuncSetAttribute(k3_out, cudaFuncAttributeMaxDynamicSharedMemorySize, K3_SMEM);

    prep_w<<<1024, 256>>>(wqkv, wout);
    k1_qkv<<<660, NT, K1_SMEM>>>(x);
    k2_attn<<<4224, 128, K2_SMEM>>>(mask);
    k3_out<<<660, NT, K3_SMEM>>>(bout, out);
}

// round 12
// speedup vs baseline: 1.0228x; 1.0228x over previous
#include <cuda_runtime.h>
#include <cuda_bf16.h>
#include <stdint.h>

// ===========================================================================
// CavAttention via mma.sync bf16 hi/lo split precision (3 merged passes)
// Round 11: B staged as pre-built mma fragments in global (direct LDG.128,
//           register-pipelined). No cp.async, no B smem, no mainloop barriers.
//   prep: wqkv/wout -> per-lane B fragment images (hi+lo packed in uint4)
//   K1:   qkv = xp @ wqkv                 (HMMA)  -> g_qkv
//   K2:   masked softmax + P@V            (SIMT)  -> g_att
//   K3:   out = att @ wout + bias         (HMMA, transposed store)
// ===========================================================================

#define HW_   8448
#define NROWS 84480

__device__ __align__(16) float g_qkv[(size_t)NROWS * 768];
__device__ __align__(16) float g_att[(size_t)NROWS * 256];
// B fragment images: [step][j(16)][lane(32)] uint4 = {r0h, r1h, r0l, r1l}
// K1: step = nt*16 + kc*4 + ks, nt<6  -> 96*16*32 uint4
// K3: step = nt*16 + kc*4 + ks, nt<2  -> 32*16*32 uint4
__device__ __align__(16) uint4 g_w1f[96 * 16 * 32];
__device__ __align__(16) uint4 g_w2f[32 * 16 * 32];

#define AP 264            // A smem pitch (bf16 elems): 528B ≡ 4 banks mod 32

// ----------------------------- helpers ------------------------------------
__device__ __forceinline__ uint32_t smem_u32(const void* p) {
    uint32_t a;
    asm("{ .reg .u64 t; cvta.to.shared.u64 t, %1; cvt.u32.u64 %0, t; }" : "=r"(a) : "l"(p));
    return a;
}
__device__ __forceinline__ float bres(float f) {
    return f - __bfloat162float(__float2bfloat16(f));
}
__device__ __forceinline__ uint32_t pack2(float a, float b) {
    return (uint32_t)__bfloat16_as_ushort(__float2bfloat16(a)) |
           ((uint32_t)__bfloat16_as_ushort(__float2bfloat16(b)) << 16);
}
__device__ __forceinline__ uint64_t pack4(float a0, float a1, float a2, float a3) {
    return (uint64_t)pack2(a0, a1) | ((uint64_t)pack2(a2, a3) << 32);
}
__device__ __forceinline__ void ldmA(uint32_t* r, uint32_t addr) {
    asm volatile("ldmatrix.sync.aligned.m8n8.x4.shared.b16 {%0,%1,%2,%3}, [%4];"
                 : "=r"(r[0]), "=r"(r[1]), "=r"(r[2]), "=r"(r[3]) : "r"(addr));
}
__device__ __forceinline__ void mma16816(float* c, const uint32_t* a, uint32_t b0, uint32_t b1) {
    asm volatile("mma.sync.aligned.m16n8k16.row.col.f32.bf16.bf16.f32 "
                 "{%0,%1,%2,%3}, {%4,%5,%6,%7}, {%8,%9}, {%0,%1,%2,%3};"
                 : "+f"(c[0]), "+f"(c[1]), "+f"(c[2]), "+f"(c[3])
                 : "r"(a[0]), "r"(a[1]), "r"(a[2]), "r"(a[3]), "r"(b0), "r"(b1));
}
// load one step's 4 B fragments (hi+lo) for this warp
__device__ __forceinline__ void loadB(uint4* b, const uint4* __restrict__ frag,
                                      int t, int j0, int lane) {
    const uint4* p = frag + ((t * 16 + j0) * 32 + lane);
    b[0] = __ldg(p); b[1] = __ldg(p + 32); b[2] = __ldg(p + 64); b[3] = __ldg(p + 96);
}

// merged-pass MMA for one k16 step: 8 ldmA + 48 MMA using fragment uint4s
__device__ __forceinline__ void mma_step(float acc[4][4][4], uint32_t aHi, uint32_t aLo,
                                         int ks, const uint4* bc) {
    uint32_t ah[4][4], al[4][4];
    #pragma unroll
    for (int i = 0; i < 4; ++i) {
        ldmA(ah[i], aHi + (uint32_t)((i * 16 * AP + ks * 16) * 2));
        ldmA(al[i], aLo + (uint32_t)((i * 16 * AP + ks * 16) * 2));
    }
    #pragma unroll
    for (int i = 0; i < 4; ++i)
        #pragma unroll
        for (int j = 0; j < 4; ++j)
            mma16816(acc[i][j], ah[i], bc[j].x, bc[j].y);
    #pragma unroll
    for (int i = 0; i < 4; ++i)
        #pragma unroll
        for (int j = 0; j < 4; ++j)
            mma16816(acc[i][j], ah[i], bc[j].z, bc[j].w);
    #pragma unroll
    for (int i = 0; i < 4; ++i)
        #pragma unroll
        for (int j = 0; j < 4; ++j)
            mma16816(acc[i][j], al[i], bc[j].x, bc[j].y);
}

// ======================= prep: weight -> fragment images ===================
// idx < 49152: K1 (96 steps * 512 lanes); else K3 (32 steps * 512 lanes)
__global__ __launch_bounds__(256) void prep_w(const float* __restrict__ wqkv,
                                              const float* __restrict__ wout) {
    int idx = blockIdx.x * 256 + threadIdx.x;      // 0..65535
    const float* W; int cols; uint4* dst; int local;
    if (idx < 49152) { W = wqkv; cols = 768; dst = g_w1f; local = idx; }
    else             { W = wout; cols = 256; dst = g_w2f; local = idx - 49152; }
    int step = local >> 9;                          // nt*16 + kc*4 + ks
    int rem  = local & 511;
    int j = rem >> 5, lane = rem & 31;
    int nt = step >> 4, kc = (step >> 2) & 3, ks = step & 3;
    int n  = nt * 128 + j * 8 + (lane >> 2);
    int kb = kc * 64 + ks * 16 + (lane & 3) * 2;
    float w0 = W[(size_t)kb * cols + n];
    float w1 = W[(size_t)(kb + 1) * cols + n];
    float w2 = W[(size_t)(kb + 8) * cols + n];
    float w3 = W[(size_t)(kb + 9) * cols + n];
    uint4 o;
    o.x = pack2(w0, w1);               // reg0 hi
    o.y = pack2(w2, w3);               // reg1 hi
    o.z = pack2(bres(w0), bres(w1));   // reg0 lo
    o.w = pack2(bres(w2), bres(w3));   // reg1 lo
    dst[local] = o;
}

// ======================= K1: QKV GEMM ======================================
// smem: AHI 0 (67584B), ALO 67584 -> 135168 total
#define K_ALO  67584
#define K1_SMEM 135168

__global__ __launch_bounds__(256, 1) void k1_qkv(const float* __restrict__ x) {
    extern __shared__ __align__(16) char sm[];
    const uint32_t sb = smem_u32(sm);
    const int tid = threadIdx.x, lane = tid & 31, wid = tid >> 5;
    const int wm = (wid & 1) * 64, wn = (wid >> 1) * 32;
    const int j0 = (wid >> 1) * 4;
    const int m0 = blockIdx.x * 128;

    // stage A slab (transposed gather from x), hi/lo bf16
    for (int e = tid; e < 128 * 64; e += 256) {
        int row = e >> 6, k4 = (e & 63) << 2;
        int r = m0 + row, g = r / 5, l = r - g * 5, b = g / HW_, hw = g - b * HW_;
        const float4 v = *(const float4*)(x + ((size_t)((b * 5 + l) * HW_ + hw)) * 256 + k4);
        uint32_t off = (uint32_t)(row * AP + k4) * 2;
        *(uint64_t*)(sm + off) = pack4(v.x, v.y, v.z, v.w);
        *(uint64_t*)(sm + K_ALO + off) = pack4(bres(v.x), bres(v.y), bres(v.z), bres(v.w));
    }
    __syncthreads();                    // ONLY barrier; A is read-only after

    const uint32_t aoff = (uint32_t)(((wm + (lane & 15)) * AP + ((lane >> 4) << 3)) * 2);

    uint4 bn[4];
    loadB(bn, g_w1f, 0, j0, lane);      // prefetch step 0
    int t = 0;
    for (int nt = 0; nt < 6; ++nt) {
        float acc[4][4][4];
        #pragma unroll
        for (int i = 0; i < 4; ++i)
            #pragma unroll
            for (int j = 0; j < 4; ++j)
                #pragma unroll
                for (int q = 0; q < 4; ++q) acc[i][j][q] = 0.f;

        #pragma unroll 1
        for (int kc = 0; kc < 4; ++kc) {
            const uint32_t aHi = sb + aoff + (uint32_t)(kc * 64 * 2);
            const uint32_t aLo = aHi + K_ALO;
            #pragma unroll
            for (int ks = 0; ks < 4; ++ks) {
                uint4 bc[4];
                bc[0] = bn[0]; bc[1] = bn[1]; bc[2] = bn[2]; bc[3] = bn[3];
                ++t;
                if (t < 96) loadB(bn, g_w1f, t, j0, lane);   // prefetch next
                mma_step(acc, aHi, aLo, ks, bc);
            }
        }

        // epilogue: fp32 to g_qkv
        #pragma unroll
        for (int i = 0; i < 4; ++i) {
            int row = m0 + wm + i * 16 + (lane >> 2);
            #pragma unroll
            for (int j = 0; j < 4; ++j) {
                int col = nt * 128 + wn + j * 8 + (lane & 3) * 2;
                float* p = g_qkv + (size_t)row * 768 + col;
                *(float2*)p = make_float2(acc[i][j][0], acc[i][j][1]);
                *(float2*)(p + 8 * 768) = make_float2(acc[i][j][2], acc[i][j][3]);
            }
        }
    }
}

// ======================= K2: masked softmax attention (SIMT) ===============
#define K2_STR 769
#define K2_SMEM (20 * K2_STR * 4 + 100 * 4 + 20 * 4)

__global__ __launch_bounds__(128) void k2_attn(const int* __restrict__ mask) {
    extern __shared__ __align__(16) float sl[];           // [20][769]
    float* sc = sl + 20 * K2_STR;                         // [4][25]
    int*   ms = (int*)(sc + 100);                         // [20]
    const int tid = threadIdx.x;
    const int r0 = blockIdx.x * 20;
    const int g0 = blockIdx.x * 4;

    for (int e = tid; e < 20; e += 128) ms[e] = mask[g0 * 5 + e];
    for (int e = tid; e < 20 * 192; e += 128) {
        int row = e / 192, c4 = (e % 192) * 4;
        const float4 v = *(const float4*)(g_qkv + (size_t)(r0 + row) * 768 + c4);
        float* d = sl + row * K2_STR + c4;
        d[0] = v.x; d[1] = v.y; d[2] = v.z; d[3] = v.w;
    }
    __syncthreads();

    const float scale = 0.17677669529663687f;
    for (int h = 0; h < 8; ++h) {
        const int hc = h * 32;
        if (tid < 100) {
            int g = tid / 25, rr = tid % 25, i = rr / 5, j = rr % 5;
            float s;
            if (ms[g * 5 + j] == 0) s = -1e30f;
            else {
                const float* q = sl + (g * 5 + i) * K2_STR + hc;
                const float* k = sl + (g * 5 + j) * K2_STR + 256 + hc;
                s = 0.f;
                #pragma unroll
                for (int d = 0; d < 32; ++d) s = fmaf(q[d], k[d], s);
                s *= scale;
            }
            sc[tid] = s;
        }
        __syncthreads();
        if (tid < 20) {
            float* r = sc + (tid / 5) * 25 + (tid % 5) * 5;
            float mx = r[0];
            #pragma unroll
            for (int j = 1; j < 5; ++j) mx = fmaxf(mx, r[j]);
            float ev[5], s = 0.f;
            #pragma unroll
            for (int j = 0; j < 5; ++j) { ev[j] = __expf(r[j] - mx); s += ev[j]; }
            float inv = 1.f / s;
            #pragma unroll
            for (int j = 0; j < 5; ++j) r[j] = ev[j] * inv;
        }
        __syncthreads();
        for (int e = tid; e < 20 * 32; e += 128) {
            int row = e >> 5, d = e & 31;
            int g = row / 5, i = row - g * 5;
            const float* p = sc + g * 25 + i * 5;
            const float* v = sl + (g * 5) * K2_STR + 512 + hc + d;
            float o = 0.f;
            #pragma unroll
            for (int j = 0; j < 5; ++j) o = fmaf(p[j], v[j * K2_STR], o);
            g_att[(size_t)(r0 + row) * 256 + hc + d] = o;
        }
        __syncthreads();
    }
}

// ======================= K3: output GEMM + bias + transposed store =========
#define K3_BIAS 135168
#define K3_SMEM 136192

__global__ __launch_bounds__(256, 1) void k3_out(const float* __restrict__ bout,
                                                 float* __restrict__ out) {
    extern __shared__ __align__(16) char sm[];
    const uint32_t sb = smem_u32(sm);
    const int tid = threadIdx.x, lane = tid & 31, wid = tid >> 5;
    const int wm = (wid & 1) * 64, wn = (wid >> 1) * 32;
    const int j0 = (wid >> 1) * 4;
    const int m0 = blockIdx.x * 128;

    if (tid < 256) ((float*)(sm + K3_BIAS))[tid] = bout[tid];

    for (int e = tid; e < 128 * 64; e += 256) {
        int row = e >> 6, k4 = (e & 63) << 2;
        const float4 v = *(const float4*)(g_att + (size_t)(m0 + row) * 256 + k4);
        uint32_t off = (uint32_t)(row * AP + k4) * 2;
        *(uint64_t*)(sm + off) = pack4(v.x, v.y, v.z, v.w);
        *(uint64_t*)(sm + K_ALO + off) = pack4(bres(v.x), bres(v.y), bres(v.z), bres(v.w));
    }
    __syncthreads();                    // ONLY barrier

    const uint32_t aoff = (uint32_t)(((wm + (lane & 15)) * AP + ((lane >> 4) << 3)) * 2);
    const float* bias = (const float*)(sm + K3_BIAS);

    uint4 bn[4];
    loadB(bn, g_w2f, 0, j0, lane);
    int t = 0;
    for (int nt = 0; nt < 2; ++nt) {
        float acc[4][4][4];
        #pragma unroll
        for (int i = 0; i < 4; ++i)
            #pragma unroll
            for (int j = 0; j < 4; ++j)
                #pragma unroll
                for (int q = 0; q < 4; ++q) acc[i][j][q] = 0.f;

        #pragma unroll 1
        for (int kc = 0; kc < 4; ++kc) {
            const uint32_t aHi = sb + aoff + (uint32_t)(kc * 64 * 2);
            const uint32_t aLo = aHi + K_ALO;
            #pragma unroll
            for (int ks = 0; ks < 4; ++ks) {
                uint4 bc[4];
                bc[0] = bn[0]; bc[1] = bn[1]; bc[2] = bn[2]; bc[3] = bn[3];
                ++t;
                if (t < 32) loadB(bn, g_w2f, t, j0, lane);
                mma_step(acc, aHi, aLo, ks, bc);
            }
        }

        // epilogue: bias + transposed store to out (B,L,H,W,C layout)
        #pragma unroll
        for (int i = 0; i < 4; ++i) {
            int r1 = m0 + wm + i * 16 + (lane >> 2);
            #pragma unroll
            for (int rr = 0; rr < 2; ++rr) {
                int r = r1 + rr * 8;
                int g = r / 5, l = r - g * 5, b = g / HW_, hw = g - b * HW_;
                float* dst = out + ((size_t)((b * 5 + l) * HW_ + hw)) * 256;
                #pragma unroll
                for (int j = 0; j < 4; ++j) {
                    int col = nt * 128 + wn + j * 8 + (lane & 3) * 2;
                    float2 o = make_float2(acc[i][j][2 * rr] + bias[col],
                                           acc[i][j][2 * rr + 1] + bias[col + 1]);
                    *(float2*)(dst + col) = o;
                }
            }
        }
    }
}

// ===========================================================================
extern "C" void kernel_launch(void* const* d_in, const int* in_sizes, int n_in,
                              void* d_out, int out_size) {
    const float* x    = (const float*)d_in[0];
    const int*   mask = (const int*)d_in[1];
    const float* wqkv = (const float*)d_in[2];
    const float* wout = (const float*)d_in[3];
    const float* bout = (const float*)d_in[4];
    float*       out  = (float*)d_out;

    cudaFuncSetAttribute(k1_qkv, cudaFuncAttributeMaxDynamicSharedMemorySize, K1_SMEM);
    cudaFuncSetAttribute(k2_attn, cudaFuncAttributeMaxDynamicSharedMemorySize, K2_SMEM);
    cudaFuncSetAttribute(k3_out, cudaFuncAttributeMaxDynamicSharedMemorySize, K3_SMEM);

    prep_w<<<256, 256>>>(wqkv, wout);
    k1_qkv<<<660, 256, K1_SMEM>>>(x);
    k2_attn<<<4224, 128, K2_SMEM>>>(mask);
    k3_out<<<660, 256, K3_SMEM>>>(bout, out);
}

// round 13
// speedup vs baseline: 1.0706x; 1.0468x over previous
#include <cuda_runtime.h>
#include <cuda_fp16.h>
#include <stdint.h>

// ===========================================================================
// CavAttention via mma.sync fp16 split precision (Ootomo-style):
//   hi*hi -> f32-accum MMA; (hi*lo' + lo'*hi) -> shared f16-accum MMA chain,
//   lo' = (f - hi) * 2^11, correction folded in epilogue with * 2^-11.
// Round 12: same 3-kernel skeleton as Round 11 (direct-LDG B fragments,
//           no mainloop barriers); only the precision/accum scheme changed.
// ===========================================================================

#define HW_   8448
#define NROWS 84480
#define LO_SCALE   2048.0f
#define LO_INV     4.8828125e-4f     // 2^-11

__device__ __align__(16) float g_qkv[(size_t)NROWS * 768];
__device__ __align__(16) float g_att[(size_t)NROWS * 256];
// B fragment images: [step][j(16)][lane(32)] uint4 = {r0h, r1h, r0l, r1l}
__device__ __align__(16) uint4 g_w1f[96 * 16 * 32];
__device__ __align__(16) uint4 g_w2f[32 * 16 * 32];

#define AP 264            // A smem pitch (fp16 elems): 528B ≡ 4 banks mod 32

// ----------------------------- helpers ------------------------------------
__device__ __forceinline__ uint32_t smem_u32(const void* p) {
    uint32_t a;
    asm("{ .reg .u64 t; cvta.to.shared.u64 t, %1; cvt.u32.u64 %0, t; }" : "=r"(a) : "l"(p));
    return a;
}
__device__ __forceinline__ float hres(float f) {      // scaled fp16 residual
    return (f - __half2float(__float2half_rn(f))) * LO_SCALE;
}
__device__ __forceinline__ uint32_t pack2h(float a, float b) {
    __half2 h = __floats2half2_rn(a, b);
    return *reinterpret_cast<uint32_t*>(&h);
}
__device__ __forceinline__ uint64_t pack4h(float a0, float a1, float a2, float a3) {
    return (uint64_t)pack2h(a0, a1) | ((uint64_t)pack2h(a2, a3) << 32);
}
__device__ __forceinline__ void ldmA(uint32_t* r, uint32_t addr) {
    asm volatile("ldmatrix.sync.aligned.m8n8.x4.shared.b16 {%0,%1,%2,%3}, [%4];"
                 : "=r"(r[0]), "=r"(r[1]), "=r"(r[2]), "=r"(r[3]) : "r"(addr));
}
// f32-accum fp16 MMA (hi*hi pass)
__device__ __forceinline__ void mmaF32(float* c, const uint32_t* a, uint32_t b0, uint32_t b1) {
    asm volatile("mma.sync.aligned.m16n8k16.row.col.f32.f16.f16.f32 "
                 "{%0,%1,%2,%3}, {%4,%5,%6,%7}, {%8,%9}, {%0,%1,%2,%3};"
                 : "+f"(c[0]), "+f"(c[1]), "+f"(c[2]), "+f"(c[3])
                 : "r"(a[0]), "r"(a[1]), "r"(a[2]), "r"(a[3]), "r"(b0), "r"(b1));
}
// f16-accum fp16 MMA (correction passes)
__device__ __forceinline__ void mmaF16(uint32_t* c, const uint32_t* a, uint32_t b0, uint32_t b1) {
    asm volatile("mma.sync.aligned.m16n8k16.row.col.f16.f16.f16.f16 "
                 "{%0,%1}, {%2,%3,%4,%5}, {%6,%7}, {%0,%1};"
                 : "+r"(c[0]), "+r"(c[1])
                 : "r"(a[0]), "r"(a[1]), "r"(a[2]), "r"(a[3]), "r"(b0), "r"(b1));
}
// load one step's 4 B fragments (hi+lo) for this warp
__device__ __forceinline__ void loadB(uint4* b, const uint4* __restrict__ frag,
                                      int t, int j0, int lane) {
    const uint4* p = frag + ((t * 16 + j0) * 32 + lane);
    b[0] = __ldg(p); b[1] = __ldg(p + 32); b[2] = __ldg(p + 64); b[3] = __ldg(p + 96);
}

// one k16 step: 8 ldmA + 16 f32-MMA (hh) + 32 f16-MMA (corrections)
__device__ __forceinline__ void mma_step(float acc[4][4][4], uint32_t accH[4][4][2],
                                         uint32_t aHi, uint32_t aLo,
                                         int ks, const uint4* bc) {
    uint32_t ah[4][4], al[4][4];
    #pragma unroll
    for (int i = 0; i < 4; ++i) {
        ldmA(ah[i], aHi + (uint32_t)((i * 16 * AP + ks * 16) * 2));
        ldmA(al[i], aLo + (uint32_t)((i * 16 * AP + ks * 16) * 2));
    }
    #pragma unroll
    for (int i = 0; i < 4; ++i)
        #pragma unroll
        for (int j = 0; j < 4; ++j)
            mmaF32(acc[i][j], ah[i], bc[j].x, bc[j].y);       // hi * hi
    #pragma unroll
    for (int i = 0; i < 4; ++i)
        #pragma unroll
        for (int j = 0; j < 4; ++j)
            mmaF16(accH[i][j], ah[i], bc[j].z, bc[j].w);      // hi * lo'
    #pragma unroll
    for (int i = 0; i < 4; ++i)
        #pragma unroll
        for (int j = 0; j < 4; ++j)
            mmaF16(accH[i][j], al[i], bc[j].x, bc[j].y);      // lo' * hi
}
// fold f16 correction into fp32 values
__device__ __forceinline__ float4 fold(const float* a, const uint32_t* ch) {
    __half2 h0 = *reinterpret_cast<const __half2*>(&ch[0]);
    __half2 h1 = *reinterpret_cast<const __half2*>(&ch[1]);
    float2 c0 = __half22float2(h0), c1 = __half22float2(h1);
    return make_float4(a[0] + c0.x * LO_INV, a[1] + c0.y * LO_INV,
                       a[2] + c1.x * LO_INV, a[3] + c1.y * LO_INV);
}

// ======================= prep: weight -> fragment images ===================
__global__ __launch_bounds__(256) void prep_w(const float* __restrict__ wqkv,
                                              const float* __restrict__ wout) {
    int idx = blockIdx.x * 256 + threadIdx.x;      // 0..65535
    const float* W; int cols; uint4* dst; int local;
    if (idx < 49152) { W = wqkv; cols = 768; dst = g_w1f; local = idx; }
    else             { W = wout; cols = 256; dst = g_w2f; local = idx - 49152; }
    int step = local >> 9;                          // nt*16 + kc*4 + ks
    int rem  = local & 511;
    int j = rem >> 5, lane = rem & 31;
    int nt = step >> 4, kc = (step >> 2) & 3, ks = step & 3;
    int n  = nt * 128 + j * 8 + (lane >> 2);
    int kb = kc * 64 + ks * 16 + (lane & 3) * 2;
    float w0 = W[(size_t)kb * cols + n];
    float w1 = W[(size_t)(kb + 1) * cols + n];
    float w2 = W[(size_t)(kb + 8) * cols + n];
    float w3 = W[(size_t)(kb + 9) * cols + n];
    uint4 o;
    o.x = pack2h(w0, w1);               // reg0 hi
    o.y = pack2h(w2, w3);               // reg1 hi
    o.z = pack2h(hres(w0), hres(w1));   // reg0 lo' (scaled)
    o.w = pack2h(hres(w2), hres(w3));   // reg1 lo'
    dst[local] = o;
}

// ======================= K1: QKV GEMM ======================================
#define K_ALO  67584
#define K1_SMEM 135168

__global__ __launch_bounds__(256, 1) void k1_qkv(const float* __restrict__ x) {
    extern __shared__ __align__(16) char sm[];
    const uint32_t sb = smem_u32(sm);
    const int tid = threadIdx.x, lane = tid & 31, wid = tid >> 5;
    const int wm = (wid & 1) * 64, wn = (wid >> 1) * 32;
    const int j0 = (wid >> 1) * 4;
    const int m0 = blockIdx.x * 128;

    // stage A slab (transposed gather from x), fp16 hi/lo'
    for (int e = tid; e < 128 * 64; e += 256) {
        int row = e >> 6, k4 = (e & 63) << 2;
        int r = m0 + row, g = r / 5, l = r - g * 5, b = g / HW_, hw = g - b * HW_;
        const float4 v = *(const float4*)(x + ((size_t)((b * 5 + l) * HW_ + hw)) * 256 + k4);
        uint32_t off = (uint32_t)(row * AP + k4) * 2;
        *(uint64_t*)(sm + off) = pack4h(v.x, v.y, v.z, v.w);
        *(uint64_t*)(sm + K_ALO + off) = pack4h(hres(v.x), hres(v.y), hres(v.z), hres(v.w));
    }
    __syncthreads();                    // ONLY barrier

    const uint32_t aoff = (uint32_t)(((wm + (lane & 15)) * AP + ((lane >> 4) << 3)) * 2);

    uint4 bn[4];
    loadB(bn, g_w1f, 0, j0, lane);      // prefetch step 0
    int t = 0;
    for (int nt = 0; nt < 6; ++nt) {
        float acc[4][4][4];
        uint32_t accH[4][4][2];
        #pragma unroll
        for (int i = 0; i < 4; ++i)
            #pragma unroll
            for (int j = 0; j < 4; ++j) {
                #pragma unroll
                for (int q = 0; q < 4; ++q) acc[i][j][q] = 0.f;
                accH[i][j][0] = 0u; accH[i][j][1] = 0u;
            }

        #pragma unroll 1
        for (int kc = 0; kc < 4; ++kc) {
            const uint32_t aHi = sb + aoff + (uint32_t)(kc * 64 * 2);
            const uint32_t aLo = aHi + K_ALO;
            #pragma unroll
            for (int ks = 0; ks < 4; ++ks) {
                uint4 bc[4];
                bc[0] = bn[0]; bc[1] = bn[1]; bc[2] = bn[2]; bc[3] = bn[3];
                ++t;
                if (t < 96) loadB(bn, g_w1f, t, j0, lane);   // prefetch next
                mma_step(acc, accH, aHi, aLo, ks, bc);
            }
        }

        // epilogue: fold correction, fp32 to g_qkv
        #pragma unroll
        for (int i = 0; i < 4; ++i) {
            int row = m0 + wm + i * 16 + (lane >> 2);
            #pragma unroll
            for (int j = 0; j < 4; ++j) {
                int col = nt * 128 + wn + j * 8 + (lane & 3) * 2;
                float4 r4 = fold(acc[i][j], accH[i][j]);
                float* p = g_qkv + (size_t)row * 768 + col;
                *(float2*)p = make_float2(r4.x, r4.y);
                *(float2*)(p + 8 * 768) = make_float2(r4.z, r4.w);
            }
        }
    }
}

// ======================= K2: masked softmax attention (SIMT) ===============
#define K2_STR 769
#define K2_SMEM (20 * K2_STR * 4 + 100 * 4 + 20 * 4)

__global__ __launch_bounds__(128) void k2_attn(const int* __restrict__ mask) {
    extern __shared__ __align__(16) float sl[];           // [20][769]
    float* sc = sl + 20 * K2_STR;                         // [4][25]
    int*   ms = (int*)(sc + 100);                         // [20]
    const int tid = threadIdx.x;
    const int r0 = blockIdx.x * 20;
    const int g0 = blockIdx.x * 4;

    for (int e = tid; e < 20; e += 128) ms[e] = mask[g0 * 5 + e];
    for (int e = tid; e < 20 * 192; e += 128) {
        int row = e / 192, c4 = (e % 192) * 4;
        const float4 v = *(const float4*)(g_qkv + (size_t)(r0 + row) * 768 + c4);
        float* d = sl + row * K2_STR + c4;
        d[0] = v.x; d[1] = v.y; d[2] = v.z; d[3] = v.w;
    }
    __syncthreads();

    const float scale = 0.17677669529663687f;
    for (int h = 0; h < 8; ++h) {
        const int hc = h * 32;
        if (tid < 100) {
            int g = tid / 25, rr = tid % 25, i = rr / 5, j = rr % 5;
            float s;
            if (ms[g * 5 + j] == 0) s = -1e30f;
            else {
                const float* q = sl + (g * 5 + i) * K2_STR + hc;
                const float* k = sl + (g * 5 + j) * K2_STR + 256 + hc;
                s = 0.f;
                #pragma unroll
                for (int d = 0; d < 32; ++d) s = fmaf(q[d], k[d], s);
                s *= scale;
            }
            sc[tid] = s;
        }
        __syncthreads();
        if (tid < 20) {
            float* r = sc + (tid / 5) * 25 + (tid % 5) * 5;
            float mx = r[0];
            #pragma unroll
            for (int j = 1; j < 5; ++j) mx = fmaxf(mx, r[j]);
            float ev[5], s = 0.f;
            #pragma unroll
            for (int j = 0; j < 5; ++j) { ev[j] = __expf(r[j] - mx); s += ev[j]; }
            float inv = 1.f / s;
            #pragma unroll
            for (int j = 0; j < 5; ++j) r[j] = ev[j] * inv;
        }
        __syncthreads();
        for (int e = tid; e < 20 * 32; e += 128) {
            int row = e >> 5, d = e & 31;
            int g = row / 5, i = row - g * 5;
            const float* p = sc + g * 25 + i * 5;
            const float* v = sl + (g * 5) * K2_STR + 512 + hc + d;
            float o = 0.f;
            #pragma unroll
            for (int j = 0; j < 5; ++j) o = fmaf(p[j], v[j * K2_STR], o);
            g_att[(size_t)(r0 + row) * 256 + hc + d] = o;
        }
        __syncthreads();
    }
}

// ======================= K3: output GEMM + bias + transposed store =========
#define K3_BIAS 135168
#define K3_SMEM 136192

__global__ __launch_bounds__(256, 1) void k3_out(const float* __restrict__ bout,
                                                 float* __restrict__ out) {
    extern __shared__ __align__(16) char sm[];
    const uint32_t sb = smem_u32(sm);
    const int tid = threadIdx.x, lane = tid & 31, wid = tid >> 5;
    const int wm = (wid & 1) * 64, wn = (wid >> 1) * 32;
    const int j0 = (wid >> 1) * 4;
    const int m0 = blockIdx.x * 128;

    if (tid < 256) ((float*)(sm + K3_BIAS))[tid] = bout[tid];

    for (int e = tid; e < 128 * 64; e += 256) {
        int row = e >> 6, k4 = (e & 63) << 2;
        const float4 v = *(const float4*)(g_att + (size_t)(m0 + row) * 256 + k4);
        uint32_t off = (uint32_t)(row * AP + k4) * 2;
        *(uint64_t*)(sm + off) = pack4h(v.x, v.y, v.z, v.w);
        *(uint64_t*)(sm + K_ALO + off) = pack4h(hres(v.x), hres(v.y), hres(v.z), hres(v.w));
    }
    __syncthreads();                    // ONLY barrier

    const uint32_t aoff = (uint32_t)(((wm + (lane & 15)) * AP + ((lane >> 4) << 3)) * 2);
    const float* bias = (const float*)(sm + K3_BIAS);

    uint4 bn[4];
    loadB(bn, g_w2f, 0, j0, lane);
    int t = 0;
    for (int nt = 0; nt < 2; ++nt) {
        float acc[4][4][4];
        uint32_t accH[4][4][2];
        #pragma unroll
        for (int i = 0; i < 4; ++i)
            #pragma unroll
            for (int j = 0; j < 4; ++j) {
                #pragma unroll
                for (int q = 0; q < 4; ++q) acc[i][j][q] = 0.f;
                accH[i][j][0] = 0u; accH[i][j][1] = 0u;
            }

        #pragma unroll 1
        for (int kc = 0; kc < 4; ++kc) {
            const uint32_t aHi = sb + aoff + (uint32_t)(kc * 64 * 2);
            const uint32_t aLo = aHi + K_ALO;
            #pragma unroll
            for (int ks = 0; ks < 4; ++ks) {
                uint4 bc[4];
                bc[0] = bn[0]; bc[1] = bn[1]; bc[2] = bn[2]; bc[3] = bn[3];
                ++t;
                if (t < 32) loadB(bn, g_w2f, t, j0, lane);
                mma_step(acc, accH, aHi, aLo, ks, bc);
            }
        }

        // epilogue: fold correction + bias + transposed store
        #pragma unroll
        for (int i = 0; i < 4; ++i) {
            int r1 = m0 + wm + i * 16 + (lane >> 2);
            #pragma unroll
            for (int j = 0; j < 4; ++j) {
                int col = nt * 128 + wn + j * 8 + (lane & 3) * 2;
                float4 r4 = fold(acc[i][j], accH[i][j]);
                #pragma unroll
                for (int rr = 0; rr < 2; ++rr) {
                    int r = r1 + rr * 8;
                    int g = r / 5, l = r - g * 5, b = g / HW_, hw = g - b * HW_;
                    float* dst = out + ((size_t)((b * 5 + l) * HW_ + hw)) * 256;
                    float2 o = make_float2((rr ? r4.z : r4.x) + bias[col],
                                           (rr ? r4.w : r4.y) + bias[col + 1]);
                    *(float2*)(dst + col) = o;
                }
            }
        }
    }
}

// ===========================================================================
extern "C" void kernel_launch(void* const* d_in, const int* in_sizes, int n_in,
                              void* d_out, int out_size) {
    const float* x    = (const float*)d_in[0];
    const int*   mask = (const int*)d_in[1];
    const float* wqkv = (const float*)d_in[2];
    const float* wout = (const float*)d_in[3];
    const float* bout = (const float*)d_in[4];
    float*       out  = (float*)d_out;

    cudaFuncSetAttribute(k1_qkv, cudaFuncAttributeMaxDynamicSharedMemorySize, K1_SMEM);
    cudaFuncSetAttribute(k2_attn, cudaFuncAttributeMaxDynamicSharedMemorySize, K2_SMEM);
    cudaFuncSetAttribute(k3_out, cudaFuncAttributeMaxDynamicSharedMemorySize, K3_SMEM);

    prep_w<<<256, 256>>>(wqkv, wout);
    k1_qkv<<<660, 256, K1_SMEM>>>(x);
    k2_attn<<<4224, 128, K2_SMEM>>>(mask);
    k3_out<<<660, 256, K3_SMEM>>>(bout, out);
}

// round 14
// speedup vs baseline: 1.1641x; 1.0873x over previous
#include <cuda_runtime.h>
#include <cuda_fp16.h>
#include <stdint.h>

// ===========================================================================
// CavAttention via mma.sync fp16 split precision (Ootomo-style):
//   hi*hi -> f32-accum MMA; (hi*lo' + lo'*hi) -> f16-accum MMA chain,
//   lo' = (f - hi) * 2^11, correction folded in epilogue with * 2^-11.
// Round 13: K2 rewritten warp-per-group (no smem, no block barriers).
//           K1/K3 unchanged from Round 12 (at the mma.sync issue wall).
// ===========================================================================

#define HW_   8448
#define NROWS 84480
#define LO_SCALE   2048.0f
#define LO_INV     4.8828125e-4f     // 2^-11

__device__ __align__(16) float g_qkv[(size_t)NROWS * 768];
__device__ __align__(16) float g_att[(size_t)NROWS * 256];
// B fragment images: [step][j(16)][lane(32)] uint4 = {r0h, r1h, r0l, r1l}
__device__ __align__(16) uint4 g_w1f[96 * 16 * 32];
__device__ __align__(16) uint4 g_w2f[32 * 16 * 32];

#define AP 264            // A smem pitch (fp16 elems): 528B ≡ 4 banks mod 32

// ----------------------------- helpers ------------------------------------
__device__ __forceinline__ uint32_t smem_u32(const void* p) {
    uint32_t a;
    asm("{ .reg .u64 t; cvta.to.shared.u64 t, %1; cvt.u32.u64 %0, t; }" : "=r"(a) : "l"(p));
    return a;
}
__device__ __forceinline__ float hres(float f) {      // scaled fp16 residual
    return (f - __half2float(__float2half_rn(f))) * LO_SCALE;
}
__device__ __forceinline__ uint32_t pack2h(float a, float b) {
    __half2 h = __floats2half2_rn(a, b);
    return *reinterpret_cast<uint32_t*>(&h);
}
__device__ __forceinline__ uint64_t pack4h(float a0, float a1, float a2, float a3) {
    return (uint64_t)pack2h(a0, a1) | ((uint64_t)pack2h(a2, a3) << 32);
}
__device__ __forceinline__ void ldmA(uint32_t* r, uint32_t addr) {
    asm volatile("ldmatrix.sync.aligned.m8n8.x4.shared.b16 {%0,%1,%2,%3}, [%4];"
                 : "=r"(r[0]), "=r"(r[1]), "=r"(r[2]), "=r"(r[3]) : "r"(addr));
}
// f32-accum fp16 MMA (hi*hi pass)
__device__ __forceinline__ void mmaF32(float* c, const uint32_t* a, uint32_t b0, uint32_t b1) {
    asm volatile("mma.sync.aligned.m16n8k16.row.col.f32.f16.f16.f32 "
                 "{%0,%1,%2,%3}, {%4,%5,%6,%7}, {%8,%9}, {%0,%1,%2,%3};"
                 : "+f"(c[0]), "+f"(c[1]), "+f"(c[2]), "+f"(c[3])
                 : "r"(a[0]), "r"(a[1]), "r"(a[2]), "r"(a[3]), "r"(b0), "r"(b1));
}
// f16-accum fp16 MMA (correction passes)
__device__ __forceinline__ void mmaF16(uint32_t* c, const uint32_t* a, uint32_t b0, uint32_t b1) {
    asm volatile("mma.sync.aligned.m16n8k16.row.col.f16.f16.f16.f16 "
                 "{%0,%1}, {%2,%3,%4,%5}, {%6,%7}, {%0,%1};"
                 : "+r"(c[0]), "+r"(c[1])
                 : "r"(a[0]), "r"(a[1]), "r"(a[2]), "r"(a[3]), "r"(b0), "r"(b1));
}
// load one step's 4 B fragments (hi+lo) for this warp
__device__ __forceinline__ void loadB(uint4* b, const uint4* __restrict__ frag,
                                      int t, int j0, int lane) {
    const uint4* p = frag + ((t * 16 + j0) * 32 + lane);
    b[0] = __ldg(p); b[1] = __ldg(p + 32); b[2] = __ldg(p + 64); b[3] = __ldg(p + 96);
}

// one k16 step: 8 ldmA + 16 f32-MMA (hh) + 32 f16-MMA (corrections)
__device__ __forceinline__ void mma_step(float acc[4][4][4], uint32_t accH[4][4][2],
                                         uint32_t aHi, uint32_t aLo,
                                         int ks, const uint4* bc) {
    uint32_t ah[4][4], al[4][4];
    #pragma unroll
    for (int i = 0; i < 4; ++i) {
        ldmA(ah[i], aHi + (uint32_t)((i * 16 * AP + ks * 16) * 2));
        ldmA(al[i], aLo + (uint32_t)((i * 16 * AP + ks * 16) * 2));
    }
    #pragma unroll
    for (int i = 0; i < 4; ++i)
        #pragma unroll
        for (int j = 0; j < 4; ++j)
            mmaF32(acc[i][j], ah[i], bc[j].x, bc[j].y);       // hi * hi
    #pragma unroll
    for (int i = 0; i < 4; ++i)
        #pragma unroll
        for (int j = 0; j < 4; ++j)
            mmaF16(accH[i][j], ah[i], bc[j].z, bc[j].w);      // hi * lo'
    #pragma unroll
    for (int i = 0; i < 4; ++i)
        #pragma unroll
        for (int j = 0; j < 4; ++j)
            mmaF16(accH[i][j], al[i], bc[j].x, bc[j].y);      // lo' * hi
}
// fold f16 correction into fp32 values
__device__ __forceinline__ float4 fold(const float* a, const uint32_t* ch) {
    __half2 h0 = *reinterpret_cast<const __half2*>(&ch[0]);
    __half2 h1 = *reinterpret_cast<const __half2*>(&ch[1]);
    float2 c0 = __half22float2(h0), c1 = __half22float2(h1);
    return make_float4(a[0] + c0.x * LO_INV, a[1] + c0.y * LO_INV,
                       a[2] + c1.x * LO_INV, a[3] + c1.y * LO_INV);
}

// ======================= prep: weight -> fragment images ===================
__global__ __launch_bounds__(256) void prep_w(const float* __restrict__ wqkv,
                                              const float* __restrict__ wout) {
    int idx = blockIdx.x * 256 + threadIdx.x;      // 0..65535
    const float* W; int cols; uint4* dst; int local;
    if (idx < 49152) { W = wqkv; cols = 768; dst = g_w1f; local = idx; }
    else             { W = wout; cols = 256; dst = g_w2f; local = idx - 49152; }
    int step = local >> 9;                          // nt*16 + kc*4 + ks
    int rem  = local & 511;
    int j = rem >> 5, lane = rem & 31;
    int nt = step >> 4, kc = (step >> 2) & 3, ks = step & 3;
    int n  = nt * 128 + j * 8 + (lane >> 2);
    int kb = kc * 64 + ks * 16 + (lane & 3) * 2;
    float w0 = W[(size_t)kb * cols + n];
    float w1 = W[(size_t)(kb + 1) * cols + n];
    float w2 = W[(size_t)(kb + 8) * cols + n];
    float w3 = W[(size_t)(kb + 9) * cols + n];
    uint4 o;
    o.x = pack2h(w0, w1);               // reg0 hi
    o.y = pack2h(w2, w3);               // reg1 hi
    o.z = pack2h(hres(w0), hres(w1));   // reg0 lo' (scaled)
    o.w = pack2h(hres(w2), hres(w3));   // reg1 lo'
    dst[local] = o;
}

// ======================= K1: QKV GEMM ======================================
#define K_ALO  67584
#define K1_SMEM 135168

__global__ __launch_bounds__(256, 1) void k1_qkv(const float* __restrict__ x) {
    extern __shared__ __align__(16) char sm[];
    const uint32_t sb = smem_u32(sm);
    const int tid = threadIdx.x, lane = tid & 31, wid = tid >> 5;
    const int wm = (wid & 1) * 64, wn = (wid >> 1) * 32;
    const int j0 = (wid >> 1) * 4;
    const int m0 = blockIdx.x * 128;

    // stage A slab (transposed gather from x), fp16 hi/lo'
    for (int e = tid; e < 128 * 64; e += 256) {
        int row = e >> 6, k4 = (e & 63) << 2;
        int r = m0 + row, g = r / 5, l = r - g * 5, b = g / HW_, hw = g - b * HW_;
        const float4 v = *(const float4*)(x + ((size_t)((b * 5 + l) * HW_ + hw)) * 256 + k4);
        uint32_t off = (uint32_t)(row * AP + k4) * 2;
        *(uint64_t*)(sm + off) = pack4h(v.x, v.y, v.z, v.w);
        *(uint64_t*)(sm + K_ALO + off) = pack4h(hres(v.x), hres(v.y), hres(v.z), hres(v.w));
    }
    __syncthreads();                    // ONLY barrier

    const uint32_t aoff = (uint32_t)(((wm + (lane & 15)) * AP + ((lane >> 4) << 3)) * 2);

    uint4 bn[4];
    loadB(bn, g_w1f, 0, j0, lane);      // prefetch step 0
    int t = 0;
    for (int nt = 0; nt < 6; ++nt) {
        float acc[4][4][4];
        uint32_t accH[4][4][2];
        #pragma unroll
        for (int i = 0; i < 4; ++i)
            #pragma unroll
            for (int j = 0; j < 4; ++j) {
                #pragma unroll
                for (int q = 0; q < 4; ++q) acc[i][j][q] = 0.f;
                accH[i][j][0] = 0u; accH[i][j][1] = 0u;
            }

        #pragma unroll 1
        for (int kc = 0; kc < 4; ++kc) {
            const uint32_t aHi = sb + aoff + (uint32_t)(kc * 64 * 2);
            const uint32_t aLo = aHi + K_ALO;
            #pragma unroll
            for (int ks = 0; ks < 4; ++ks) {
                uint4 bc[4];
                bc[0] = bn[0]; bc[1] = bn[1]; bc[2] = bn[2]; bc[3] = bn[3];
                ++t;
                if (t < 96) loadB(bn, g_w1f, t, j0, lane);   // prefetch next
                mma_step(acc, accH, aHi, aLo, ks, bc);
            }
        }

        // epilogue: fold correction, fp32 to g_qkv
        #pragma unroll
        for (int i = 0; i < 4; ++i) {
            int row = m0 + wm + i * 16 + (lane >> 2);
            #pragma unroll
            for (int j = 0; j < 4; ++j) {
                int col = nt * 128 + wn + j * 8 + (lane & 3) * 2;
                float4 r4 = fold(acc[i][j], accH[i][j]);
                float* p = g_qkv + (size_t)row * 768 + col;
                *(float2*)p = make_float2(r4.x, r4.y);
                *(float2*)(p + 8 * 768) = make_float2(r4.z, r4.w);
            }
        }
    }
}

// ======================= K2: masked softmax attention (warp-per-group) =====
// One warp handles one (b,h,w) group: lane = head dim. No smem, no barriers.
__global__ __launch_bounds__(128) void k2_attn(const int* __restrict__ mask) {
    const int lane = threadIdx.x & 31;
    const int g = blockIdx.x * 4 + (threadIdx.x >> 5);
    const float scale = 0.17677669529663687f;
    const size_t rbase = (size_t)g * 5 * 768;

    int mk[5];
    #pragma unroll
    for (int j = 0; j < 5; ++j) mk[j] = mask[g * 5 + j];

    #pragma unroll 1
    for (int h = 0; h < 8; ++h) {
        const float* p = g_qkv + rbase + h * 32 + lane;
        float q[5], k[5], v[5];
        #pragma unroll
        for (int i = 0; i < 5; ++i) {
            q[i] = p[i * 768];
            k[i] = p[i * 768 + 256];
            v[i] = p[i * 768 + 512];
        }
        // 25 dot products over the 32 lanes (butterfly reduce)
        float s[5][5];
        #pragma unroll
        for (int i = 0; i < 5; ++i)
            #pragma unroll
            for (int j = 0; j < 5; ++j)
                s[i][j] = q[i] * k[j];
        #pragma unroll
        for (int o = 16; o > 0; o >>= 1)
            #pragma unroll
            for (int i = 0; i < 5; ++i)
                #pragma unroll
                for (int j = 0; j < 5; ++j)
                    s[i][j] += __shfl_xor_sync(0xffffffffu, s[i][j], o);
        // masked softmax per row + PV (uniform across lanes except v)
        #pragma unroll
        for (int i = 0; i < 5; ++i) {
            float sv[5], mx = -1e30f;
            #pragma unroll
            for (int j = 0; j < 5; ++j) {
                sv[j] = mk[j] ? s[i][j] * scale : -1e30f;
                mx = fmaxf(mx, sv[j]);
            }
            float e[5], sum = 0.f;
            #pragma unroll
            for (int j = 0; j < 5; ++j) { e[j] = __expf(sv[j] - mx); sum += e[j]; }
            float inv = 1.f / sum;
            float o_ = 0.f;
            #pragma unroll
            for (int j = 0; j < 5; ++j) o_ = fmaf(e[j] * inv, v[j], o_);
            g_att[(size_t)(g * 5 + i) * 256 + h * 32 + lane] = o_;
        }
    }
}

// ======================= K3: output GEMM + bias + transposed store =========
#define K3_BIAS 135168
#define K3_SMEM 136192

__global__ __launch_bounds__(256, 1) void k3_out(const float* __restrict__ bout,
                                                 float* __restrict__ out) {
    extern __shared__ __align__(16) char sm[];
    const uint32_t sb = smem_u32(sm);
    const int tid = threadIdx.x, lane = tid & 31, wid = tid >> 5;
    const int wm = (wid & 1) * 64, wn = (wid >> 1) * 32;
    const int j0 = (wid >> 1) * 4;
    const int m0 = blockIdx.x * 128;

    if (tid < 256) ((float*)(sm + K3_BIAS))[tid] = bout[tid];

    for (int e = tid; e < 128 * 64; e += 256) {
        int row = e >> 6, k4 = (e & 63) << 2;
        const float4 v = *(const float4*)(g_att + (size_t)(m0 + row) * 256 + k4);
        uint32_t off = (uint32_t)(row * AP + k4) * 2;
        *(uint64_t*)(sm + off) = pack4h(v.x, v.y, v.z, v.w);
        *(uint64_t*)(sm + K_ALO + off) = pack4h(hres(v.x), hres(v.y), hres(v.z), hres(v.w));
    }
    __syncthreads();                    // ONLY barrier

    const uint32_t aoff = (uint32_t)(((wm + (lane & 15)) * AP + ((lane >> 4) << 3)) * 2);
    const float* bias = (const float*)(sm + K3_BIAS);

    uint4 bn[4];
    loadB(bn, g_w2f, 0, j0, lane);
    int t = 0;
    for (int nt = 0; nt < 2; ++nt) {
        float acc[4][4][4];
        uint32_t accH[4][4][2];
        #pragma unroll
        for (int i = 0; i < 4; ++i)
            #pragma unroll
            for (int j = 0; j < 4; ++j) {
                #pragma unroll
                for (int q = 0; q < 4; ++q) acc[i][j][q] = 0.f;
                accH[i][j][0] = 0u; accH[i][j][1] = 0u;
            }

        #pragma unroll 1
        for (int kc = 0; kc < 4; ++kc) {
            const uint32_t aHi = sb + aoff + (uint32_t)(kc * 64 * 2);
            const uint32_t aLo = aHi + K_ALO;
            #pragma unroll
            for (int ks = 0; ks < 4; ++ks) {
                uint4 bc[4];
                bc[0] = bn[0]; bc[1] = bn[1]; bc[2] = bn[2]; bc[3] = bn[3];
                ++t;
                if (t < 32) loadB(bn, g_w2f, t, j0, lane);
                mma_step(acc, accH, aHi, aLo, ks, bc);
            }
        }

        // epilogue: fold correction + bias + transposed store
        #pragma unroll
        for (int i = 0; i < 4; ++i) {
            int r1 = m0 + wm + i * 16 + (lane >> 2);
            #pragma unroll
            for (int j = 0; j < 4; ++j) {
                int col = nt * 128 + wn + j * 8 + (lane & 3) * 2;
                float4 r4 = fold(acc[i][j], accH[i][j]);
                #pragma unroll
                for (int rr = 0; rr < 2; ++rr) {
                    int r = r1 + rr * 8;
                    int g = r / 5, l = r - g * 5, b = g / HW_, hw = g - b * HW_;
                    float* dst = out + ((size_t)((b * 5 + l) * HW_ + hw)) * 256;
                    float2 o = make_float2((rr ? r4.z : r4.x) + bias[col],
                                           (rr ? r4.w : r4.y) + bias[col + 1]);
                    *(float2*)(dst + col) = o;
                }
            }
        }
    }
}

// ===========================================================================
extern "C" void kernel_launch(void* const* d_in, const int* in_sizes, int n_in,
                              void* d_out, int out_size) {
    const float* x    = (const float*)d_in[0];
    const int*   mask = (const int*)d_in[1];
    const float* wqkv = (const float*)d_in[2];
    const float* wout = (const float*)d_in[3];
    const float* bout = (const float*)d_in[4];
    float*       out  = (float*)d_out;

    cudaFuncSetAttribute(k1_qkv, cudaFuncAttributeMaxDynamicSharedMemorySize, K1_SMEM);
    cudaFuncSetAttribute(k3_out, cudaFuncAttributeMaxDynamicSharedMemorySize, K3_SMEM);

    prep_w<<<256, 256>>>(wqkv, wout);
    k1_qkv<<<660, 256, K1_SMEM>>>(x);
    k2_attn<<<4224, 128>>>(mask);
    k3_out<<<660, 256, K3_SMEM>>>(bout, out);
}

// round 16
// speedup vs baseline: 1.3582x; 1.1667x over previous
#include <cuda_runtime.h>
#include <cuda_fp16.h>
#include <stdint.h>

// ===========================================================================
// CavAttention via mma.sync fp16 split precision, 2-PASS scheme:
//   C ≈ Ahi·Bhi (f32-accum) + Alo'·Bhi (f16-accum, lo' = residual * 2^11)
// The Ahi·Blo term is dropped: its contribution is a zero-mean random sum
// ~3e-4 relative — well under the 1e-3 threshold. 32 MMA instr per k16-step
// instead of 48 -> 1.5x on both GEMMs (which sit at the mma.sync issue wall).
// Round 14: K2 warp-per-group (R13), B fragments hi-only (uint2).
// ===========================================================================

#define HW_   8448
#define NROWS 84480
#define LO_SCALE   2048.0f
#define LO_INV     4.8828125e-4f     // 2^-11

__device__ __align__(16) float g_qkv[(size_t)NROWS * 768];
__device__ __align__(16) float g_att[(size_t)NROWS * 256];
// B fragment images (hi only): [step][j(16)][lane(32)] uint2 = {r0h, r1h}
__device__ __align__(16) uint2 g_w1f[96 * 16 * 32];
__device__ __align__(16) uint2 g_w2f[32 * 16 * 32];

#define AP 264            // A smem pitch (fp16 elems): 528B ≡ 4 banks mod 32

// ----------------------------- helpers ------------------------------------
__device__ __forceinline__ uint32_t smem_u32(const void* p) {
    uint32_t a;
    asm("{ .reg .u64 t; cvta.to.shared.u64 t, %1; cvt.u32.u64 %0, t; }" : "=r"(a) : "l"(p));
    return a;
}
__device__ __forceinline__ float hres(float f) {      // scaled fp16 residual
    return (f - __half2float(__float2half_rn(f))) * LO_SCALE;
}
__device__ __forceinline__ uint32_t pack2h(float a, float b) {
    __half2 h = __floats2half2_rn(a, b);
    return *reinterpret_cast<uint32_t*>(&h);
}
__device__ __forceinline__ uint64_t pack4h(float a0, float a1, float a2, float a3) {
    return (uint64_t)pack2h(a0, a1) | ((uint64_t)pack2h(a2, a3) << 32);
}
__device__ __forceinline__ void ldmA(uint32_t* r, uint32_t addr) {
    asm volatile("ldmatrix.sync.aligned.m8n8.x4.shared.b16 {%0,%1,%2,%3}, [%4];"
                 : "=r"(r[0]), "=r"(r[1]), "=r"(r[2]), "=r"(r[3]) : "r"(addr));
}
// f32-accum fp16 MMA (hi*hi pass)
__device__ __forceinline__ void mmaF32(float* c, const uint32_t* a, uint32_t b0, uint32_t b1) {
    asm volatile("mma.sync.aligned.m16n8k16.row.col.f32.f16.f16.f32 "
                 "{%0,%1,%2,%3}, {%4,%5,%6,%7}, {%8,%9}, {%0,%1,%2,%3};"
                 : "+f"(c[0]), "+f"(c[1]), "+f"(c[2]), "+f"(c[3])
                 : "r"(a[0]), "r"(a[1]), "r"(a[2]), "r"(a[3]), "r"(b0), "r"(b1));
}
// f16-accum fp16 MMA (correction pass)
__device__ __forceinline__ void mmaF16(uint32_t* c, const uint32_t* a, uint32_t b0, uint32_t b1) {
    asm volatile("mma.sync.aligned.m16n8k16.row.col.f16.f16.f16.f16 "
                 "{%0,%1}, {%2,%3,%4,%5}, {%6,%7}, {%0,%1};"
                 : "+r"(c[0]), "+r"(c[1])
                 : "r"(a[0]), "r"(a[1]), "r"(a[2]), "r"(a[3]), "r"(b0), "r"(b1));
}
// load one step's 4 B fragments (hi) for this warp
__device__ __forceinline__ void loadB(uint2* b, const uint2* __restrict__ frag,
                                      int t, int j0, int lane) {
    const uint2* p = frag + ((t * 16 + j0) * 32 + lane);
    b[0] = __ldg(p); b[1] = __ldg(p + 32); b[2] = __ldg(p + 64); b[3] = __ldg(p + 96);
}

// one k16 step: 8 ldmA + 16 f32-MMA (hi*hi) + 16 f16-MMA (lo'*hi)
__device__ __forceinline__ void mma_step(float acc[4][4][4], uint32_t accH[4][4][2],
                                         uint32_t aHi, uint32_t aLo,
                                         int ks, const uint2* bc) {
    uint32_t ah[4][4], al[4][4];
    #pragma unroll
    for (int i = 0; i < 4; ++i) {
        ldmA(ah[i], aHi + (uint32_t)((i * 16 * AP + ks * 16) * 2));
        ldmA(al[i], aLo + (uint32_t)((i * 16 * AP + ks * 16) * 2));
    }
    #pragma unroll
    for (int i = 0; i < 4; ++i)
        #pragma unroll
        for (int j = 0; j < 4; ++j)
            mmaF32(acc[i][j], ah[i], bc[j].x, bc[j].y);       // hi * hi
    #pragma unroll
    for (int i = 0; i < 4; ++i)
        #pragma unroll
        for (int j = 0; j < 4; ++j)
            mmaF16(accH[i][j], al[i], bc[j].x, bc[j].y);      // lo' * hi
}
// fold f16 correction into fp32 values
__device__ __forceinline__ float4 fold(const float* a, const uint32_t* ch) {
    __half2 h0 = *reinterpret_cast<const __half2*>(&ch[0]);
    __half2 h1 = *reinterpret_cast<const __half2*>(&ch[1]);
    float2 c0 = __half22float2(h0), c1 = __half22float2(h1);
    return make_float4(a[0] + c0.x * LO_INV, a[1] + c0.y * LO_INV,
                       a[2] + c1.x * LO_INV, a[3] + c1.y * LO_INV);
}

// ======================= prep: weight -> fragment images ===================
__global__ __launch_bounds__(256) void prep_w(const float* __restrict__ wqkv,
                                              const float* __restrict__ wout) {
    int idx = blockIdx.x * 256 + threadIdx.x;      // 0..65535
    const float* W; int cols; uint2* dst; int local;
    if (idx < 49152) { W = wqkv; cols = 768; dst = g_w1f; local = idx; }
    else             { W = wout; cols = 256; dst = g_w2f; local = idx - 49152; }
    int step = local >> 9;                          // nt*16 + kc*4 + ks
    int rem  = local & 511;
    int j = rem >> 5, lane = rem & 31;
    int nt = step >> 4, kc = (step >> 2) & 3, ks = step & 3;
    int n  = nt * 128 + j * 8 + (lane >> 2);
    int kb = kc * 64 + ks * 16 + (lane & 3) * 2;
    float w0 = W[(size_t)kb * cols + n];
    float w1 = W[(size_t)(kb + 1) * cols + n];
    float w2 = W[(size_t)(kb + 8) * cols + n];
    float w3 = W[(size_t)(kb + 9) * cols + n];
    uint2 o;
    o.x = pack2h(w0, w1);               // reg0 hi
    o.y = pack2h(w2, w3);               // reg1 hi
    dst[local] = o;
}

// ======================= K1: QKV GEMM ======================================
#define K_ALO  67584
#define K1_SMEM 135168

__global__ __launch_bounds__(256, 1) void k1_qkv(const float* __restrict__ x) {
    extern __shared__ __align__(16) char sm[];
    const uint32_t sb = smem_u32(sm);
    const int tid = threadIdx.x, lane = tid & 31, wid = tid >> 5;
    const int wm = (wid & 1) * 64, wn = (wid >> 1) * 32;
    const int j0 = (wid >> 1) * 4;
    const int m0 = blockIdx.x * 128;

    // stage A slab (transposed gather from x), fp16 hi/lo'
    for (int e = tid; e < 128 * 64; e += 256) {
        int row = e >> 6, k4 = (e & 63) << 2;
        int r = m0 + row, g = r / 5, l = r - g * 5, b = g / HW_, hw = g - b * HW_;
        const float4 v = *(const float4*)(x + ((size_t)((b * 5 + l) * HW_ + hw)) * 256 + k4);
        uint32_t off = (uint32_t)(row * AP + k4) * 2;
        *(uint64_t*)(sm + off) = pack4h(v.x, v.y, v.z, v.w);
        *(uint64_t*)(sm + K_ALO + off) = pack4h(hres(v.x), hres(v.y), hres(v.z), hres(v.w));
    }
    __syncthreads();                    // ONLY barrier

    const uint32_t aoff = (uint32_t)(((wm + (lane & 15)) * AP + ((lane >> 4) << 3)) * 2);

    uint2 bn[4];
    loadB(bn, g_w1f, 0, j0, lane);      // prefetch step 0
    int t = 0;
    for (int nt = 0; nt < 6; ++nt) {
        float acc[4][4][4];
        uint32_t accH[4][4][2];
        #pragma unroll
        for (int i = 0; i < 4; ++i)
            #pragma unroll
            for (int j = 0; j < 4; ++j) {
                #pragma unroll
                for (int q = 0; q < 4; ++q) acc[i][j][q] = 0.f;
                accH[i][j][0] = 0u; accH[i][j][1] = 0u;
            }

        #pragma unroll 1
        for (int kc = 0; kc < 4; ++kc) {
            const uint32_t aHi = sb + aoff + (uint32_t)(kc * 64 * 2);
            const uint32_t aLo = aHi + K_ALO;
            #pragma unroll
            for (int ks = 0; ks < 4; ++ks) {
                uint2 bc[4];
                bc[0] = bn[0]; bc[1] = bn[1]; bc[2] = bn[2]; bc[3] = bn[3];
                ++t;
                if (t < 96) loadB(bn, g_w1f, t, j0, lane);   // prefetch next
                mma_step(acc, accH, aHi, aLo, ks, bc);
            }
        }

        // epilogue: fold correction, fp32 to g_qkv
        #pragma unroll
        for (int i = 0; i < 4; ++i) {
            int row = m0 + wm + i * 16 + (lane >> 2);
            #pragma unroll
            for (int j = 0; j < 4; ++j) {
                int col = nt * 128 + wn + j * 8 + (lane & 3) * 2;
                float4 r4 = fold(acc[i][j], accH[i][j]);
                float* p = g_qkv + (size_t)row * 768 + col;
                *(float2*)p = make_float2(r4.x, r4.y);
                *(float2*)(p + 8 * 768) = make_float2(r4.z, r4.w);
            }
        }
    }
}

// ======================= K2: masked softmax attention (warp-per-group) =====
__global__ __launch_bounds__(128) void k2_attn(const int* __restrict__ mask) {
    const int lane = threadIdx.x & 31;
    const int g = blockIdx.x * 4 + (threadIdx.x >> 5);
    const float scale = 0.17677669529663687f;
    const size_t rbase = (size_t)g * 5 * 768;

    int mk[5];
    #pragma unroll
    for (int j = 0; j < 5; ++j) mk[j] = mask[g * 5 + j];

    #pragma unroll 1
    for (int h = 0; h < 8; ++h) {
        const float* p = g_qkv + rbase + h * 32 + lane;
        float q[5], k[5], v[5];
        #pragma unroll
        for (int i = 0; i < 5; ++i) {
            q[i] = p[i * 768];
            k[i] = p[i * 768 + 256];
            v[i] = p[i * 768 + 512];
        }
        float s[5][5];
        #pragma unroll
        for (int i = 0; i < 5; ++i)
            #pragma unroll
            for (int j = 0; j < 5; ++j)
                s[i][j] = q[i] * k[j];
        #pragma unroll
        for (int o = 16; o > 0; o >>= 1)
            #pragma unroll
            for (int i = 0; i < 5; ++i)
                #pragma unroll
                for (int j = 0; j < 5; ++j)
                    s[i][j] += __shfl_xor_sync(0xffffffffu, s[i][j], o);
        #pragma unroll
        for (int i = 0; i < 5; ++i) {
            float sv[5], mx = -1e30f;
            #pragma unroll
            for (int j = 0; j < 5; ++j) {
                sv[j] = mk[j] ? s[i][j] * scale : -1e30f;
                mx = fmaxf(mx, sv[j]);
            }
            float e[5], sum = 0.f;
            #pragma unroll
            for (int j = 0; j < 5; ++j) { e[j] = __expf(sv[j] - mx); sum += e[j]; }
            float inv = 1.f / sum;
            float o_ = 0.f;
            #pragma unroll
            for (int j = 0; j < 5; ++j) o_ = fmaf(e[j] * inv, v[j], o_);
            g_att[(size_t)(g * 5 + i) * 256 + h * 32 + lane] = o_;
        }
    }
}

// ======================= K3: output GEMM + bias + transposed store =========
#define K3_BIAS 135168
#define K3_SMEM 136192

__global__ __launch_bounds__(256, 1) void k3_out(const float* __restrict__ bout,
                                                 float* __restrict__ out) {
    extern __shared__ __align__(16) char sm[];
    const uint32_t sb = smem_u32(sm);
    const int tid = threadIdx.x, lane = tid & 31, wid = tid >> 5;
    const int wm = (wid & 1) * 64, wn = (wid >> 1) * 32;
    const int j0 = (wid >> 1) * 4;
    const int m0 = blockIdx.x * 128;

    if (tid < 256) ((float*)(sm + K3_BIAS))[tid] = bout[tid];

    for (int e = tid; e < 128 * 64; e += 256) {
        int row = e >> 6, k4 = (e & 63) << 2;
        const float4 v = *(const float4*)(g_att + (size_t)(m0 + row) * 256 + k4);
        uint32_t off = (uint32_t)(row * AP + k4) * 2;
        *(uint64_t*)(sm + off) = pack4h(v.x, v.y, v.z, v.w);
        *(uint64_t*)(sm + K_ALO + off) = pack4h(hres(v.x), hres(v.y), hres(v.z), hres(v.w));
    }
    __syncthreads();                    // ONLY barrier

    const uint32_t aoff = (uint32_t)(((wm + (lane & 15)) * AP + ((lane >> 4) << 3)) * 2);
    const float* bias = (const float*)(sm + K3_BIAS);

    uint2 bn[4];
    loadB(bn, g_w2f, 0, j0, lane);
    int t = 0;
    for (int nt = 0; nt < 2; ++nt) {
        float acc[4][4][4];
        uint32_t accH[4][4][2];
        #pragma unroll
        for (int i = 0; i < 4; ++i)
            #pragma unroll
            for (int j = 0; j < 4; ++j) {
                #pragma unroll
                for (int q = 0; q < 4; ++q) acc[i][j][q] = 0.f;
                accH[i][j][0] = 0u; accH[i][j][1] = 0u;
            }

        #pragma unroll 1
        for (int kc = 0; kc < 4; ++kc) {
            const uint32_t aHi = sb + aoff + (uint32_t)(kc * 64 * 2);
            const uint32_t aLo = aHi + K_ALO;
            #pragma unroll
            for (int ks = 0; ks < 4; ++ks) {
                uint2 bc[4];
                bc[0] = bn[0]; bc[1] = bn[1]; bc[2] = bn[2]; bc[3] = bn[3];
                ++t;
                if (t < 32) loadB(bn, g_w2f, t, j0, lane);
                mma_step(acc, accH, aHi, aLo, ks, bc);
            }
        }

        // epilogue: fold correction + bias + transposed store
        #pragma unroll
        for (int i = 0; i < 4; ++i) {
            int r1 = m0 + wm + i * 16 + (lane >> 2);
            #pragma unroll
            for (int j = 0; j < 4; ++j) {
                int col = nt * 128 + wn + j * 8 + (lane & 3) * 2;
                float4 r4 = fold(acc[i][j], accH[i][j]);
                #pragma unroll
                for (int rr = 0; rr < 2; ++rr) {
                    int r = r1 + rr * 8;
                    int g = r / 5, l = r - g * 5, b = g / HW_, hw = g - b * HW_;
                    float* dst = out + ((size_t)((b * 5 + l) * HW_ + hw)) * 256;
                    float2 o = make_float2((rr ? r4.z : r4.x) + bias[col],
                                           (rr ? r4.w : r4.y) + bias[col + 1]);
                    *(float2*)(dst + col) = o;
                }
            }
        }
    }
}

// ===========================================================================
extern "C" void kernel_launch(void* const* d_in, const int* in_sizes, int n_in,
                              void* d_out, int out_size) {
    const float* x    = (const float*)d_in[0];
    const int*   mask = (const int*)d_in[1];
    const float* wqkv = (const float*)d_in[2];
    const float* wout = (const float*)d_in[3];
    const float* bout = (const float*)d_in[4];
    float*       out  = (float*)d_out;

    cudaFuncSetAttribute(k1_qkv, cudaFuncAttributeMaxDynamicSharedMemorySize, K1_SMEM);
    cudaFuncSetAttribute(k3_out, cudaFuncAttributeMaxDynamicSharedMemorySize, K3_SMEM);

    prep_w<<<256, 256>>>(wqkv, wout);
    k1_qkv<<<660, 256, K1_SMEM>>>(x);
    k2_attn<<<4224, 128>>>(mask);
    k3_out<<<660, 256, K3_SMEM>>>(bout, out);
}

// round 17
// speedup vs baseline: 1.5548x; 1.1447x over previous
#include <cuda_runtime.h>
#include <cuda_fp16.h>
#include <stdint.h>

// ===========================================================================
// CavAttention via mma.sync fp16 split precision, 2-PASS scheme:
//   C ≈ Ahi·Bhi (f32-accum) + Alo'·Bhi (f16-accum, lo' = residual * 2^11)
// Round 16: K2 rewritten 4-heads-per-warp: lane=(head,dim-octet), float4 per
//   lane, 3-level 8-lane butterfly reduction (75 shfl / 4 heads vs 500).
//   K1/K3 unchanged (at the 2-pass mma.sync issue wall).
// ===========================================================================

#define HW_   8448
#define NROWS 84480
#define LO_SCALE   2048.0f
#define LO_INV     4.8828125e-4f     // 2^-11

__device__ __align__(16) float g_qkv[(size_t)NROWS * 768];
__device__ __align__(16) float g_att[(size_t)NROWS * 256];
// B fragment images (hi only): [step][j(16)][lane(32)] uint2 = {r0h, r1h}
__device__ __align__(16) uint2 g_w1f[96 * 16 * 32];
__device__ __align__(16) uint2 g_w2f[32 * 16 * 32];

#define AP 264            // A smem pitch (fp16 elems): 528B ≡ 4 banks mod 32

// ----------------------------- helpers ------------------------------------
__device__ __forceinline__ uint32_t smem_u32(const void* p) {
    uint32_t a;
    asm("{ .reg .u64 t; cvta.to.shared.u64 t, %1; cvt.u32.u64 %0, t; }" : "=r"(a) : "l"(p));
    return a;
}
__device__ __forceinline__ float hres(float f) {      // scaled fp16 residual
    return (f - __half2float(__float2half_rn(f))) * LO_SCALE;
}
__device__ __forceinline__ uint32_t pack2h(float a, float b) {
    __half2 h = __floats2half2_rn(a, b);
    return *reinterpret_cast<uint32_t*>(&h);
}
__device__ __forceinline__ uint64_t pack4h(float a0, float a1, float a2, float a3) {
    return (uint64_t)pack2h(a0, a1) | ((uint64_t)pack2h(a2, a3) << 32);
}
__device__ __forceinline__ void ldmA(uint32_t* r, uint32_t addr) {
    asm volatile("ldmatrix.sync.aligned.m8n8.x4.shared.b16 {%0,%1,%2,%3}, [%4];"
                 : "=r"(r[0]), "=r"(r[1]), "=r"(r[2]), "=r"(r[3]) : "r"(addr));
}
// f32-accum fp16 MMA (hi*hi pass)
__device__ __forceinline__ void mmaF32(float* c, const uint32_t* a, uint32_t b0, uint32_t b1) {
    asm volatile("mma.sync.aligned.m16n8k16.row.col.f32.f16.f16.f32 "
                 "{%0,%1,%2,%3}, {%4,%5,%6,%7}, {%8,%9}, {%0,%1,%2,%3};"
                 : "+f"(c[0]), "+f"(c[1]), "+f"(c[2]), "+f"(c[3])
                 : "r"(a[0]), "r"(a[1]), "r"(a[2]), "r"(a[3]), "r"(b0), "r"(b1));
}
// f16-accum fp16 MMA (correction pass)
__device__ __forceinline__ void mmaF16(uint32_t* c, const uint32_t* a, uint32_t b0, uint32_t b1) {
    asm volatile("mma.sync.aligned.m16n8k16.row.col.f16.f16.f16.f16 "
                 "{%0,%1}, {%2,%3,%4,%5}, {%6,%7}, {%0,%1};"
                 : "+r"(c[0]), "+r"(c[1])
                 : "r"(a[0]), "r"(a[1]), "r"(a[2]), "r"(a[3]), "r"(b0), "r"(b1));
}
// load one step's 4 B fragments (hi) for this warp
__device__ __forceinline__ void loadB(uint2* b, const uint2* __restrict__ frag,
                                      int t, int j0, int lane) {
    const uint2* p = frag + ((t * 16 + j0) * 32 + lane);
    b[0] = __ldg(p); b[1] = __ldg(p + 32); b[2] = __ldg(p + 64); b[3] = __ldg(p + 96);
}

// one k16 step: 8 ldmA + 16 f32-MMA (hi*hi) + 16 f16-MMA (lo'*hi)
__device__ __forceinline__ void mma_step(float acc[4][4][4], uint32_t accH[4][4][2],
                                         uint32_t aHi, uint32_t aLo,
                                         int ks, const uint2* bc) {
    uint32_t ah[4][4], al[4][4];
    #pragma unroll
    for (int i = 0; i < 4; ++i) {
        ldmA(ah[i], aHi + (uint32_t)((i * 16 * AP + ks * 16) * 2));
        ldmA(al[i], aLo + (uint32_t)((i * 16 * AP + ks * 16) * 2));
    }
    #pragma unroll
    for (int i = 0; i < 4; ++i)
        #pragma unroll
        for (int j = 0; j < 4; ++j)
            mmaF32(acc[i][j], ah[i], bc[j].x, bc[j].y);       // hi * hi
    #pragma unroll
    for (int i = 0; i < 4; ++i)
        #pragma unroll
        for (int j = 0; j < 4; ++j)
            mmaF16(accH[i][j], al[i], bc[j].x, bc[j].y);      // lo' * hi
}
// fold f16 correction into fp32 values
__device__ __forceinline__ float4 fold(const float* a, const uint32_t* ch) {
    __half2 h0 = *reinterpret_cast<const __half2*>(&ch[0]);
    __half2 h1 = *reinterpret_cast<const __half2*>(&ch[1]);
    float2 c0 = __half22float2(h0), c1 = __half22float2(h1);
    return make_float4(a[0] + c0.x * LO_INV, a[1] + c0.y * LO_INV,
                       a[2] + c1.x * LO_INV, a[3] + c1.y * LO_INV);
}

// ======================= prep: weight -> fragment images ===================
__global__ __launch_bounds__(256) void prep_w(const float* __restrict__ wqkv,
                                              const float* __restrict__ wout) {
    int idx = blockIdx.x * 256 + threadIdx.x;      // 0..65535
    const float* W; int cols; uint2* dst; int local;
    if (idx < 49152) { W = wqkv; cols = 768; dst = g_w1f; local = idx; }
    else             { W = wout; cols = 256; dst = g_w2f; local = idx - 49152; }
    int step = local >> 9;                          // nt*16 + kc*4 + ks
    int rem  = local & 511;
    int j = rem >> 5, lane = rem & 31;
    int nt = step >> 4, kc = (step >> 2) & 3, ks = step & 3;
    int n  = nt * 128 + j * 8 + (lane >> 2);
    int kb = kc * 64 + ks * 16 + (lane & 3) * 2;
    float w0 = W[(size_t)kb * cols + n];
    float w1 = W[(size_t)(kb + 1) * cols + n];
    float w2 = W[(size_t)(kb + 8) * cols + n];
    float w3 = W[(size_t)(kb + 9) * cols + n];
    uint2 o;
    o.x = pack2h(w0, w1);               // reg0 hi
    o.y = pack2h(w2, w3);               // reg1 hi
    dst[local] = o;
}

// ======================= K1: QKV GEMM ======================================
#define K_ALO  67584
#define K1_SMEM 135168

__global__ __launch_bounds__(256, 1) void k1_qkv(const float* __restrict__ x) {
    extern __shared__ __align__(16) char sm[];
    const uint32_t sb = smem_u32(sm);
    const int tid = threadIdx.x, lane = tid & 31, wid = tid >> 5;
    const int wm = (wid & 1) * 64, wn = (wid >> 1) * 32;
    const int j0 = (wid >> 1) * 4;
    const int m0 = blockIdx.x * 128;

    // stage A slab (transposed gather from x), fp16 hi/lo'
    for (int e = tid; e < 128 * 64; e += 256) {
        int row = e >> 6, k4 = (e & 63) << 2;
        int r = m0 + row, g = r / 5, l = r - g * 5, b = g / HW_, hw = g - b * HW_;
        const float4 v = *(const float4*)(x + ((size_t)((b * 5 + l) * HW_ + hw)) * 256 + k4);
        uint32_t off = (uint32_t)(row * AP + k4) * 2;
        *(uint64_t*)(sm + off) = pack4h(v.x, v.y, v.z, v.w);
        *(uint64_t*)(sm + K_ALO + off) = pack4h(hres(v.x), hres(v.y), hres(v.z), hres(v.w));
    }
    __syncthreads();                    // ONLY barrier

    const uint32_t aoff = (uint32_t)(((wm + (lane & 15)) * AP + ((lane >> 4) << 3)) * 2);

    uint2 bn[4];
    loadB(bn, g_w1f, 0, j0, lane);      // prefetch step 0
    int t = 0;
    for (int nt = 0; nt < 6; ++nt) {
        float acc[4][4][4];
        uint32_t accH[4][4][2];
        #pragma unroll
        for (int i = 0; i < 4; ++i)
            #pragma unroll
            for (int j = 0; j < 4; ++j) {
                #pragma unroll
                for (int q = 0; q < 4; ++q) acc[i][j][q] = 0.f;
                accH[i][j][0] = 0u; accH[i][j][1] = 0u;
            }

        #pragma unroll 1
        for (int kc = 0; kc < 4; ++kc) {
            const uint32_t aHi = sb + aoff + (uint32_t)(kc * 64 * 2);
            const uint32_t aLo = aHi + K_ALO;
            #pragma unroll
            for (int ks = 0; ks < 4; ++ks) {
                uint2 bc[4];
                bc[0] = bn[0]; bc[1] = bn[1]; bc[2] = bn[2]; bc[3] = bn[3];
                ++t;
                if (t < 96) loadB(bn, g_w1f, t, j0, lane);   // prefetch next
                mma_step(acc, accH, aHi, aLo, ks, bc);
            }
        }

        // epilogue: fold correction, fp32 to g_qkv
        #pragma unroll
        for (int i = 0; i < 4; ++i) {
            int row = m0 + wm + i * 16 + (lane >> 2);
            #pragma unroll
            for (int j = 0; j < 4; ++j) {
                int col = nt * 128 + wn + j * 8 + (lane & 3) * 2;
                float4 r4 = fold(acc[i][j], accH[i][j]);
                float* p = g_qkv + (size_t)row * 768 + col;
                *(float2*)p = make_float2(r4.x, r4.y);
                *(float2*)(p + 8 * 768) = make_float2(r4.z, r4.w);
            }
        }
    }
}

// ======================= K2: masked softmax attention ======================
// One warp per group; lane = (head-in-quad hq[2b], dim-octet d8[3b]).
// Each lane owns 4 dims (float4). Scores reduced over 8-lane segments with
// 3 butterfly levels (offsets 1,2,4). Two head-quads per warp cover 8 heads.
__global__ __launch_bounds__(128) void k2_attn(const int* __restrict__ mask) {
    const int lane = threadIdx.x & 31;
    const int g = blockIdx.x * 4 + (threadIdx.x >> 5);
    const float scale = 0.17677669529663687f;
    const size_t rbase = (size_t)g * 5 * 768;

    int mk[5];
    #pragma unroll
    for (int j = 0; j < 5; ++j) mk[j] = mask[g * 5 + j];

    #pragma unroll 1
    for (int quad = 0; quad < 2; ++quad) {
        // column offset for this lane: quad*128 + lane*4  (contiguous per warp)
        const float* p = g_qkv + rbase + quad * 128 + lane * 4;
        float4 q[5], k[5], v[5];
        #pragma unroll
        for (int i = 0; i < 5; ++i) {
            q[i] = *(const float4*)(p + i * 768);
            k[i] = *(const float4*)(p + i * 768 + 256);
            v[i] = *(const float4*)(p + i * 768 + 512);
        }
        // 25 scores, each reduced over the 8-lane segment (same head)
        float s[5][5];
        #pragma unroll
        for (int i = 0; i < 5; ++i)
            #pragma unroll
            for (int j = 0; j < 5; ++j) {
                float d = q[i].x * k[j].x;
                d = fmaf(q[i].y, k[j].y, d);
                d = fmaf(q[i].z, k[j].z, d);
                d = fmaf(q[i].w, k[j].w, d);
                s[i][j] = d;
            }
        #pragma unroll
        for (int o = 1; o < 8; o <<= 1)
            #pragma unroll
            for (int i = 0; i < 5; ++i)
                #pragma unroll
                for (int j = 0; j < 5; ++j)
                    s[i][j] += __shfl_xor_sync(0xffffffffu, s[i][j], o);
        // masked softmax per row + PV (uniform within 8-lane segment)
        #pragma unroll
        for (int i = 0; i < 5; ++i) {
            float sv[5], mx = -1e30f;
            #pragma unroll
            for (int j = 0; j < 5; ++j) {
                sv[j] = mk[j] ? s[i][j] * scale : -1e30f;
                mx = fmaxf(mx, sv[j]);
            }
            float e[5], sum = 0.f;
            #pragma unroll
            for (int j = 0; j < 5; ++j) { e[j] = __expf(sv[j] - mx); sum += e[j]; }
            float inv = 1.f / sum;
            float4 o_ = make_float4(0.f, 0.f, 0.f, 0.f);
            #pragma unroll
            for (int j = 0; j < 5; ++j) {
                float w = e[j] * inv;
                o_.x = fmaf(w, v[j].x, o_.x);
                o_.y = fmaf(w, v[j].y, o_.y);
                o_.z = fmaf(w, v[j].z, o_.z);
                o_.w = fmaf(w, v[j].w, o_.w);
            }
            *(float4*)(g_att + (size_t)(g * 5 + i) * 256 + quad * 128 + lane * 4) = o_;
        }
    }
}

// ======================= K3: output GEMM + bias + transposed store =========
#define K3_BIAS 135168
#define K3_SMEM 136192

__global__ __launch_bounds__(256, 1) void k3_out(const float* __restrict__ bout,
                                                 float* __restrict__ out) {
    extern __shared__ __align__(16) char sm[];
    const uint32_t sb = smem_u32(sm);
    const int tid = threadIdx.x, lane = tid & 31, wid = tid >> 5;
    const int wm = (wid & 1) * 64, wn = (wid >> 1) * 32;
    const int j0 = (wid >> 1) * 4;
    const int m0 = blockIdx.x * 128;

    if (tid < 256) ((float*)(sm + K3_BIAS))[tid] = bout[tid];

    for (int e = tid; e < 128 * 64; e += 256) {
        int row = e >> 6, k4 = (e & 63) << 2;
        const float4 v = *(const float4*)(g_att + (size_t)(m0 + row) * 256 + k4);
        uint32_t off = (uint32_t)(row * AP + k4) * 2;
        *(uint64_t*)(sm + off) = pack4h(v.x, v.y, v.z, v.w);
        *(uint64_t*)(sm + K_ALO + off) = pack4h(hres(v.x), hres(v.y), hres(v.z), hres(v.w));
    }
    __syncthreads();                    // ONLY barrier

    const uint32_t aoff = (uint32_t)(((wm + (lane & 15)) * AP + ((lane >> 4) << 3)) * 2);
    const float* bias = (const float*)(sm + K3_BIAS);

    uint2 bn[4];
    loadB(bn, g_w2f, 0, j0, lane);
    int t = 0;
    for (int nt = 0; nt < 2; ++nt) {
        float acc[4][4][4];
        uint32_t accH[4][4][2];
        #pragma unroll
        for (int i = 0; i < 4; ++i)
            #pragma unroll
            for (int j = 0; j < 4; ++j) {
                #pragma unroll
                for (int q = 0; q < 4; ++q) acc[i][j][q] = 0.f;
                accH[i][j][0] = 0u; accH[i][j][1] = 0u;
            }

        #pragma unroll 1
        for (int kc = 0; kc < 4; ++kc) {
            const uint32_t aHi = sb + aoff + (uint32_t)(kc * 64 * 2);
            const uint32_t aLo = aHi + K_ALO;
            #pragma unroll
            for (int ks = 0; ks < 4; ++ks) {
                uint2 bc[4];
                bc[0] = bn[0]; bc[1] = bn[1]; bc[2] = bn[2]; bc[3] = bn[3];
                ++t;
                if (t < 32) loadB(bn, g_w2f, t, j0, lane);
                mma_step(acc, accH, aHi, aLo, ks, bc);
            }
        }

        // epilogue: fold correction + bias + transposed store
        #pragma unroll
        for (int i = 0; i < 4; ++i) {
            int r1 = m0 + wm + i * 16 + (lane >> 2);
            #pragma unroll
            for (int j = 0; j < 4; ++j) {
                int col = nt * 128 + wn + j * 8 + (lane & 3) * 2;
                float4 r4 = fold(acc[i][j], accH[i][j]);
                #pragma unroll
                for (int rr = 0; rr < 2; ++rr) {
                    int r = r1 + rr * 8;
                    int g = r / 5, l = r - g * 5, b = g / HW_, hw = g - b * HW_;
                    float* dst = out + ((size_t)((b * 5 + l) * HW_ + hw)) * 256;
                    float2 o = make_float2((rr ? r4.z : r4.x) + bias[col],
                                           (rr ? r4.w : r4.y) + bias[col + 1]);
                    *(float2*)(dst + col) = o;
                }
            }
        }
    }
}

// ===========================================================================
extern "C" void kernel_launch(void* const* d_in, const int* in_sizes, int n_in,
                              void* d_out, int out_size) {
    const float* x    = (const float*)d_in[0];
    const int*   mask = (const int*)d_in[1];
    const float* wqkv = (const float*)d_in[2];
    const float* wout = (const float*)d_in[3];
    const float* bout = (const float*)d_in[4];
    float*       out  = (float*)d_out;

    cudaFuncSetAttribute(k1_qkv, cudaFuncAttributeMaxDynamicSharedMemorySize, K1_SMEM);
    cudaFuncSetAttribute(k3_out, cudaFuncAttributeMaxDynamicSharedMemorySize, K3_SMEM);

    prep_w<<<256, 256>>>(wqkv, wout);
    k1_qkv<<<660, 256, K1_SMEM>>>(x);
    k2_attn<<<4224, 128>>>(mask);
    k3_out<<<660, 256, K3_SMEM>>>(bout, out);
}